// round 1
// baseline (speedup 1.0000x reference)
#include <cuda_runtime.h>
#include <math.h>

// ---------------- problem constants ----------------
#define NB      2
#define TLEN    1024
#define DMODEL  512
#define DIN     1024      // D_INNER
#define DTRANK  64
#define DSTATE  16
#define NPROJ   96        // DTRANK + 2*DSTATE

#define R0 (NB*TLEN)      // 2048 rows at scale 0
#define R1 (NB*TLEN/2)    // 1024
#define R2 (NB*TLEN/4)    // 512

// ---------------- scratch (static device memory; no allocs) ----------------
__device__ float g_xz   [R0*2*DIN];   // in_proj output: cols[0,1024)=x_in, [1024,2048)=gate
__device__ float g_xs1  [R1*DIN];
__device__ float g_xs2  [R2*DIN];
__device__ float g_xc0  [R0*DIN];
__device__ float g_xc1  [R1*DIN];
__device__ float g_xc2  [R2*DIN];
__device__ float g_proj0[R0*NPROJ];
__device__ float g_proj1[R1*NPROJ];
__device__ float g_proj2[R2*NPROJ];
__device__ float g_dt0  [R0*DIN];
__device__ float g_dt1  [R1*DIN];
__device__ float g_dt2  [R2*DIN];
__device__ float g_y0   [R0*DIN];
__device__ float g_y1   [R1*DIN];
__device__ float g_y2   [R2*DIN];
__device__ float g_fused[R0*DIN];
__device__ float g_ctx  [R0*DIN];
__device__ float g_h1   [R0*(DIN/2)];
__device__ float g_act  [R0*DIN];
__device__ float g_pre  [R0*DMODEL];
__device__ float g_w    [4];

// ---------------- math helpers ----------------
// FMA-only exp (avoids MUFU.EX2; MUFU is the scan bottleneck otherwise).
// rel err ~1e-7 over the clamped range.
__device__ __forceinline__ float fexp(float x) {
    float t = x * 1.4426950408889634f;           // log2(e)
    t = fminf(fmaxf(t, -126.0f), 126.0f);
    float fi = rintf(t);
    float f  = t - fi;                           // [-0.5, 0.5]
    float p  = 1.5403530393e-4f;                 // 2^f Taylor (deg 6)
    p = fmaf(p, f, 1.3333558146e-3f);
    p = fmaf(p, f, 9.6181291076e-3f);
    p = fmaf(p, f, 5.5504108664e-2f);
    p = fmaf(p, f, 2.4022650695e-1f);
    p = fmaf(p, f, 6.9314718056e-1f);
    p = fmaf(p, f, 1.0f);
    float sc = __int_as_float(((int)fi + 127) << 23);
    return sc * p;
}

__device__ __forceinline__ float sigmoidf_(float x) {
    return __fdividef(1.0f, 1.0f + fexp(-x));
}
__device__ __forceinline__ float siluf_(float x) {
    return x * sigmoidf_(x);
}
__device__ __forceinline__ float softplusf_(float x) {
    // logaddexp(x, 0) = max(x,0) + log1p(exp(-|x|))
    return fmaxf(x, 0.0f) + log1pf(fexp(-fabsf(x)));
}

// ---------------- generic NT GEMM: C[m,n] = epi( sum_k A[m,k]*W[n,k] ) ----------------
// 64x64 tile, BK=16, 256 threads, 4x4 per-thread micro-tile.
// mode: 0=none, 1=+bias[n], 2=silu, 3=sigmoid(acc)*e1*silu(e2), 4=+e1 (residual)
__global__ void gemm_nt(const float* __restrict__ A, int lda,
                        const float* __restrict__ W, int ldb,
                        float* __restrict__ C, int ldc,
                        int M, int N, int K,
                        const float* __restrict__ bias, int mode,
                        const float* __restrict__ e1, int lde1,
                        const float* __restrict__ e2, int lde2)
{
    __shared__ float sA[16][68];
    __shared__ float sB[16][68];

    const int tid = threadIdx.x;          // 0..255
    const int tx  = tid & 15;
    const int ty  = tid >> 4;
    const int m0  = blockIdx.y * 64;
    const int n0  = blockIdx.x * 64;

    const int lr = tid >> 2;              // 0..63 row within tile
    const int lk = (tid & 3) * 4;         // k quad 0/4/8/12

    const float* Aload = A + (size_t)(m0 + lr) * lda + lk;
    const bool nvalid  = (n0 + lr) < N;
    const float* Wload = W + (size_t)(n0 + lr) * ldb + lk;

    float acc[4][4];
    #pragma unroll
    for (int i = 0; i < 4; i++)
        #pragma unroll
        for (int j = 0; j < 4; j++) acc[i][j] = 0.0f;

    for (int k0 = 0; k0 < K; k0 += 16) {
        float4 av = *(const float4*)(Aload + k0);
        float4 wv = nvalid ? *(const float4*)(Wload + k0) : make_float4(0.f,0.f,0.f,0.f);
        sA[lk+0][lr] = av.x; sA[lk+1][lr] = av.y; sA[lk+2][lr] = av.z; sA[lk+3][lr] = av.w;
        sB[lk+0][lr] = wv.x; sB[lk+1][lr] = wv.y; sB[lk+2][lr] = wv.z; sB[lk+3][lr] = wv.w;
        __syncthreads();
        #pragma unroll
        for (int kk = 0; kk < 16; kk++) {
            float4 a4 = *(const float4*)&sA[kk][ty * 4];
            float4 b4 = *(const float4*)&sB[kk][tx * 4];
            float ar[4] = {a4.x, a4.y, a4.z, a4.w};
            float br[4] = {b4.x, b4.y, b4.z, b4.w};
            #pragma unroll
            for (int i = 0; i < 4; i++)
                #pragma unroll
                for (int j = 0; j < 4; j++)
                    acc[i][j] = fmaf(ar[i], br[j], acc[i][j]);
        }
        __syncthreads();
    }

    #pragma unroll
    for (int i = 0; i < 4; i++) {
        int m = m0 + ty * 4 + i;
        #pragma unroll
        for (int j = 0; j < 4; j++) {
            int n = n0 + tx * 4 + j;
            if (n >= N) continue;
            float v = acc[i][j];
            if (mode == 1)      v += bias[n];
            else if (mode == 2) v = siluf_(v);
            else if (mode == 3) v = sigmoidf_(v) * e1[(size_t)m * lde1 + n]
                                                 * siluf_(e2[(size_t)m * lde2 + n]);
            else if (mode == 4) v += e1[(size_t)m * lde1 + n];
            C[(size_t)m * ldc + n] = v;
        }
    }
}

// ---------------- downsample by 2 (mean of pairs) ----------------
__global__ void down2(const float* __restrict__ src, int lds,
                      float* __restrict__ dst, int Tout)
{
    int idx = blockIdx.x * blockDim.x + threadIdx.x;
    int total = NB * Tout * DIN;
    if (idx >= total) return;
    int d = idx & (DIN - 1);
    int t = (idx >> 10) % Tout;
    int b = idx / (Tout * DIN);
    const float* p = src + (size_t)(b * 2 * Tout + 2 * t) * lds + d;
    dst[idx] = 0.5f * (p[0] + p[lds]);
}

// ---------------- depthwise causal conv (K=4) + bias + SiLU ----------------
__global__ void conv_silu(const float* __restrict__ xin, int ldx,
                          const float* __restrict__ w,      // [DIN,4] for this scale
                          const float* __restrict__ bias,   // [DIN]
                          float* __restrict__ xc, int Tl)
{
    int idx = blockIdx.x * blockDim.x + threadIdx.x;
    int total = NB * Tl * DIN;
    if (idx >= total) return;
    int d = idx & (DIN - 1);
    int t = (idx >> 10) % Tl;
    int b = idx / (Tl * DIN);
    const float* base = xin + (size_t)(b * Tl) * ldx + d;
    float acc = bias[d];
    #pragma unroll
    for (int k = 0; k < 4; k++) {
        int tt = t + k - 3;
        if (tt >= 0) acc = fmaf(w[d * 4 + k], base[(size_t)tt * ldx], acc);
    }
    xc[idx] = siluf_(acc);
}

// ---------------- selective scan ----------------
// block: 256 thr = 16 d-channels x 16 states; grid: NB * (DIN/16) blocks.
// Recurrence (matches ref's log-space scan exactly):
//   h_t = max(exp(sp(dt)*A_j),1e-38) * h_{t-1} + max(sp(dt)*B_t[j]*xc_t, 1e-38)
//   y_t[d] = sum_j C_t[j]*h_t + D[d]*xc_t[d]
__global__ void scan_kernel(const float* __restrict__ xc,
                            const float* __restrict__ proj,   // [.., 96] cols: dt_raw|B|C
                            const float* __restrict__ dt,     // [.., DIN] (raw, pre-softplus)
                            const float* __restrict__ A_log,  // [DIN,16] (this scale)
                            const float* __restrict__ Dp,     // [DIN]
                            float* __restrict__ y, int Tl)
{
    const int j    = threadIdx.x & 15;
    const int dloc = threadIdx.x >> 4;       // 0..15
    const int b    = blockIdx.x >> 6;        // 64 d-groups per batch
    const int d0   = (blockIdx.x & 63) * 16;
    const int d    = d0 + dloc;

    __shared__ float s_dt[64][16];
    __shared__ float s_xc[64][16];
    __shared__ float s_B [64][17];
    __shared__ float s_C [64][17];

    const float Aj = -expf(A_log[d * 16 + j]);   // once per thread; precise path OK
    const float Dv = Dp[d];
    float h = 0.0f;

    for (int t0 = 0; t0 < Tl; t0 += 64) {
        for (int i = threadIdx.x; i < 64 * 16; i += 256) {
            int tt = i >> 4, dl = i & 15;
            int gt = t0 + tt;
            size_t rbase = (size_t)(b * Tl + gt);
            s_dt[tt][dl] = softplusf_(dt[rbase * DIN + d0 + dl]);
            s_xc[tt][dl] = xc[rbase * DIN + d0 + dl];
            const float* pr = proj + rbase * NPROJ;
            s_B[tt][dl] = pr[DTRANK + dl];
            s_C[tt][dl] = pr[DTRANK + DSTATE + dl];
        }
        __syncthreads();
        #pragma unroll 4
        for (int tt = 0; tt < 64; tt++) {
            float dtv = s_dt[tt][dloc];
            float xcv = s_xc[tt][dloc];
            float dA  = fmaxf(fexp(dtv * Aj), 1e-38f);
            float dBx = fmaxf(dtv * s_B[tt][j] * xcv, 1e-38f);
            h = fmaf(dA, h, dBx);
            float part = s_C[tt][j] * h;
            part += __shfl_xor_sync(0xffffffffu, part, 8);
            part += __shfl_xor_sync(0xffffffffu, part, 4);
            part += __shfl_xor_sync(0xffffffffu, part, 2);
            part += __shfl_xor_sync(0xffffffffu, part, 1);
            if (j == 0)
                y[(size_t)(b * Tl + t0 + tt) * DIN + d] = fmaf(Dv, xcv, part);
        }
        __syncthreads();
    }
}

// ---------------- softmax of the 3 scale weights ----------------
__global__ void compute_w(const float* __restrict__ sw, float* __restrict__ gw)
{
    float a = sw[0], b = sw[1], c = sw[2];
    float m = fmaxf(a, fmaxf(b, c));
    float ea = expf(a - m), eb = expf(b - m), ec = expf(c - m);
    float s = ea + eb + ec;
    gw[0] = ea / s; gw[1] = eb / s; gw[2] = ec / s;
}

// ---------------- fuse: weighted sum + mean (with nearest-upsample) ----------------
__global__ void fuse_kernel(const float* __restrict__ y0,
                            const float* __restrict__ y1,
                            const float* __restrict__ y2,
                            const float* __restrict__ gw,
                            float* __restrict__ fused,
                            float* __restrict__ ctx)
{
    int idx = blockIdx.x * blockDim.x + threadIdx.x;   // R0*DIN total
    int d = idx & (DIN - 1);
    int t = (idx >> 10) & (TLEN - 1);
    int b = idx >> 20;
    float o0 = y0[idx];
    float o1 = y1[(size_t)(b * (TLEN/2) + (t >> 1)) * DIN + d];
    float o2 = y2[(size_t)(b * (TLEN/4) + (t >> 2)) * DIN + d];
    float w0 = gw[0], w1 = gw[1], w2 = gw[2];
    fused[idx] = w0 * o0 + w1 * o1 + w2 * o2;
    ctx[idx]   = (o0 + o1 + o2) * (1.0f / 3.0f);
}

// ---------------- LayerNorm over last dim (512) ----------------
__global__ void ln_kernel(const float* __restrict__ pre,
                          const float* __restrict__ gamma,
                          const float* __restrict__ beta,
                          float* __restrict__ out)
{
    int row = blockIdx.x;                 // 2048 rows
    int tid = threadIdx.x;                // 256 threads
    const float* r = pre + (size_t)row * DMODEL;
    float v1 = r[tid], v2 = r[tid + 256];
    float s  = v1 + v2;
    float q  = v1 * v1 + v2 * v2;
    #pragma unroll
    for (int o = 16; o > 0; o >>= 1) {
        s += __shfl_xor_sync(0xffffffffu, s, o);
        q += __shfl_xor_sync(0xffffffffu, q, o);
    }
    __shared__ float sh[8], sh2[8];
    int wid = tid >> 5, lane = tid & 31;
    if (lane == 0) { sh[wid] = s; sh2[wid] = q; }
    __syncthreads();
    if (tid == 0) {
        float ts = 0.f, tq = 0.f;
        #pragma unroll
        for (int i = 0; i < 8; i++) { ts += sh[i]; tq += sh2[i]; }
        sh[0] = ts; sh2[0] = tq;
    }
    __syncthreads();
    float mu  = sh[0] * (1.0f / DMODEL);
    float var = sh2[0] * (1.0f / DMODEL) - mu * mu;
    float inv = rsqrtf(var + 1e-5f);
    float* o = out + (size_t)row * DMODEL;
    o[tid]       = (v1 - mu) * inv * gamma[tid]       + beta[tid];
    o[tid + 256] = (v2 - mu) * inv * gamma[tid + 256] + beta[tid + 256];
}

// ---------------- driver ----------------
extern "C" void kernel_launch(void* const* d_in, const int* in_sizes, int n_in,
                              void* d_out, int out_size)
{
    const float* x        = (const float*)d_in[0];   // [2,1024,512]
    const float* in_proj  = (const float*)d_in[1];   // [2048,512]
    const float* conv_w   = (const float*)d_in[2];   // [3,1024,1,4]
    const float* conv_b   = (const float*)d_in[3];   // [3,1024]
    const float* xproj_w  = (const float*)d_in[4];   // [3,96,1024]
    const float* dtproj_w = (const float*)d_in[5];   // [3,1024,64]
    const float* dtproj_b = (const float*)d_in[6];   // [3,1024]
    const float* A_log    = (const float*)d_in[7];   // [3,1024,16]
    const float* D_p      = (const float*)d_in[8];   // [3,1024]
    const float* sw       = (const float*)d_in[9];   // [3]
    const float* cg_w1    = (const float*)d_in[10];  // [512,1024]
    const float* cg_w2    = (const float*)d_in[11];  // [1024,512]
    const float* out_w    = (const float*)d_in[12];  // [512,1024]
    const float* ln_g     = (const float*)d_in[13];  // [512]
    const float* ln_b     = (const float*)d_in[14];  // [512]
    float* out            = (float*)d_out;

    float *xz, *xs1, *xs2, *xc0, *xc1, *xc2, *p0, *p1, *p2;
    float *dt0, *dt1, *dt2, *y0, *y1, *y2, *fused, *ctx, *h1, *act, *pre, *gw;
    cudaGetSymbolAddress((void**)&xz,   g_xz);
    cudaGetSymbolAddress((void**)&xs1,  g_xs1);
    cudaGetSymbolAddress((void**)&xs2,  g_xs2);
    cudaGetSymbolAddress((void**)&xc0,  g_xc0);
    cudaGetSymbolAddress((void**)&xc1,  g_xc1);
    cudaGetSymbolAddress((void**)&xc2,  g_xc2);
    cudaGetSymbolAddress((void**)&p0,   g_proj0);
    cudaGetSymbolAddress((void**)&p1,   g_proj1);
    cudaGetSymbolAddress((void**)&p2,   g_proj2);
    cudaGetSymbolAddress((void**)&dt0,  g_dt0);
    cudaGetSymbolAddress((void**)&dt1,  g_dt1);
    cudaGetSymbolAddress((void**)&dt2,  g_dt2);
    cudaGetSymbolAddress((void**)&y0,   g_y0);
    cudaGetSymbolAddress((void**)&y1,   g_y1);
    cudaGetSymbolAddress((void**)&y2,   g_y2);
    cudaGetSymbolAddress((void**)&fused,g_fused);
    cudaGetSymbolAddress((void**)&ctx,  g_ctx);
    cudaGetSymbolAddress((void**)&h1,   g_h1);
    cudaGetSymbolAddress((void**)&act,  g_act);
    cudaGetSymbolAddress((void**)&pre,  g_pre);
    cudaGetSymbolAddress((void**)&gw,   g_w);

    // 1. in_proj: xz[2048,2048] = x @ in_proj_w.T
    gemm_nt<<<dim3(32, 32), 256>>>(x, DMODEL, in_proj, DMODEL, xz, 2*DIN,
                                   R0, 2*DIN, DMODEL, nullptr, 0, nullptr, 0, nullptr, 0);

    // 2. downsample x_in (cols [0,1024) of xz)
    down2<<<(R1*DIN)/256, 256>>>(xz, 2*DIN, xs1, TLEN/2);
    down2<<<(R2*DIN)/256, 256>>>(xs1, DIN, xs2, TLEN/4);

    // 3. per-scale depthwise conv + SiLU
    conv_silu<<<(R0*DIN)/256, 256>>>(xz,  2*DIN, conv_w,          conv_b,          xc0, TLEN);
    conv_silu<<<(R1*DIN)/256, 256>>>(xs1, DIN,   conv_w + 4096,   conv_b + 1024,   xc1, TLEN/2);
    conv_silu<<<(R2*DIN)/256, 256>>>(xs2, DIN,   conv_w + 8192,   conv_b + 2048,   xc2, TLEN/4);

    // 4. xproj: proj = xc @ xproj_w[s].T  (N=96)
    gemm_nt<<<dim3(2, 32), 256>>>(xc0, DIN, xproj_w,          DIN, p0, NPROJ, R0, NPROJ, DIN, nullptr, 0, nullptr, 0, nullptr, 0);
    gemm_nt<<<dim3(2, 16), 256>>>(xc1, DIN, xproj_w +  98304, DIN, p1, NPROJ, R1, NPROJ, DIN, nullptr, 0, nullptr, 0, nullptr, 0);
    gemm_nt<<<dim3(2,  8), 256>>>(xc2, DIN, xproj_w + 196608, DIN, p2, NPROJ, R2, NPROJ, DIN, nullptr, 0, nullptr, 0, nullptr, 0);

    // 5. dtproj: dt = proj[:, :64] @ dtproj_w[s].T + bias  (K=64)
    gemm_nt<<<dim3(16, 32), 256>>>(p0, NPROJ, dtproj_w,          DTRANK, dt0, DIN, R0, DIN, DTRANK, dtproj_b,        1, nullptr, 0, nullptr, 0);
    gemm_nt<<<dim3(16, 16), 256>>>(p1, NPROJ, dtproj_w +  65536, DTRANK, dt1, DIN, R1, DIN, DTRANK, dtproj_b + 1024, 1, nullptr, 0, nullptr, 0);
    gemm_nt<<<dim3(16,  8), 256>>>(p2, NPROJ, dtproj_w + 131072, DTRANK, dt2, DIN, R2, DIN, DTRANK, dtproj_b + 2048, 1, nullptr, 0, nullptr, 0);

    // 6. selective scan per scale
    scan_kernel<<<128, 256>>>(xc0, p0, dt0, A_log,         D_p,        y0, TLEN);
    scan_kernel<<<128, 256>>>(xc1, p1, dt1, A_log + 16384, D_p + 1024, y1, TLEN/2);
    scan_kernel<<<128, 256>>>(xc2, p2, dt2, A_log + 32768, D_p + 2048, y2, TLEN/4);

    // 7. fuse (softmax weights + weighted sum + mean with upsample)
    compute_w<<<1, 1>>>(sw, gw);
    fuse_kernel<<<(R0*DIN)/256, 256>>>(y0, y1, y2, gw, fused, ctx);

    // 8. context gate: h1 = silu(ctx @ cg_w1.T); act = sigmoid(h1 @ cg_w2.T) * fused * silu(gate)
    gemm_nt<<<dim3(8, 32), 256>>>(ctx, DIN, cg_w1, DIN, h1, DIN/2, R0, DIN/2, DIN,
                                  nullptr, 2, nullptr, 0, nullptr, 0);
    gemm_nt<<<dim3(16, 32), 256>>>(h1, DIN/2, cg_w2, DIN/2, act, DIN, R0, DIN, DIN/2,
                                   nullptr, 3, fused, DIN, xz + DIN, 2*DIN);

    // 9. out_proj + residual
    gemm_nt<<<dim3(8, 32), 256>>>(act, DIN, out_w, DIN, pre, DMODEL, R0, DMODEL, DIN,
                                  nullptr, 4, x, DMODEL, nullptr, 0);

    // 10. LayerNorm
    ln_kernel<<<R0, 256>>>(pre, ln_g, ln_b, out);
}

// round 3
// speedup vs baseline: 1.2273x; 1.2273x over previous
#include <cuda_runtime.h>
#include <cuda_bf16.h>
#include <stdint.h>
#include <math.h>

// ---------------- problem constants ----------------
#define NB      2
#define TLEN    1024
#define DMODEL  512
#define DIN     1024      // D_INNER
#define DTRANK  64
#define DSTATE  16
#define NPROJ   96        // DTRANK + 2*DSTATE

#define R0 (NB*TLEN)      // 2048 rows at scale 0
#define R1 (NB*TLEN/2)    // 1024
#define R2 (NB*TLEN/4)    // 512

// ---------------- scratch (static device memory; no allocs) ----------------
__device__ float g_xz   [R0*2*DIN];
__device__ float g_xs1  [R1*DIN];
__device__ float g_xs2  [R2*DIN];
__device__ float g_xc0  [R0*DIN];
__device__ float g_xc1  [R1*DIN];
__device__ float g_xc2  [R2*DIN];
__device__ float g_proj0[R0*NPROJ];
__device__ float g_proj1[R1*NPROJ];
__device__ float g_proj2[R2*NPROJ];
__device__ float g_dt0  [R0*DIN];
__device__ float g_dt1  [R1*DIN];
__device__ float g_dt2  [R2*DIN];
__device__ float g_y0   [R0*DIN];
__device__ float g_y1   [R1*DIN];
__device__ float g_y2   [R2*DIN];
__device__ float g_fused[R0*DIN];
__device__ float g_ctx  [R0*DIN];
__device__ float g_h1   [R0*(DIN/2)];
__device__ float g_act  [R0*DIN];
__device__ float g_pre  [R0*DMODEL];
__device__ float g_w    [4];

// ---------------- math helpers ----------------
__device__ __forceinline__ float fexp(float x) {
    float t = x * 1.4426950408889634f;
    t = fminf(fmaxf(t, -126.0f), 126.0f);
    float fi = rintf(t);
    float f  = t - fi;
    float p  = 1.5403530393e-4f;
    p = fmaf(p, f, 1.3333558146e-3f);
    p = fmaf(p, f, 9.6181291076e-3f);
    p = fmaf(p, f, 5.5504108664e-2f);
    p = fmaf(p, f, 2.4022650695e-1f);
    p = fmaf(p, f, 6.9314718056e-1f);
    p = fmaf(p, f, 1.0f);
    float sc = __int_as_float(((int)fi + 127) << 23);
    return sc * p;
}
__device__ __forceinline__ float sigmoidf_(float x) {
    return __fdividef(1.0f, 1.0f + fexp(-x));
}
__device__ __forceinline__ float siluf_(float x) { return x * sigmoidf_(x); }
__device__ __forceinline__ float softplusf_(float x) {
    return fmaxf(x, 0.0f) + log1pf(fexp(-fabsf(x)));
}

// ---------------- tensor-core NT GEMM (bf16x3 split, fp32 accum) ----------------
// C[m,n] = epi( sum_k A[m,k]*W[n,k] ), A row-major [M,K], W row-major [N,K].
// BM=128, BN=64, BK=16, 256 threads = 8 warps (4 m-warps x 2 n-warps, 32x32/warp).
// mode: 0=none, 1=+bias[n], 2=silu, 3=sigmoid(acc)*e1*silu(e2), 4=+e1
#define SSTR 24   // smem row stride in bf16 elems (48B: conflict-free ldmatrix rows)

__device__ __forceinline__ void ldm_x4(unsigned int* r, const __nv_bfloat16* p) {
    unsigned int a = (unsigned int)__cvta_generic_to_shared(p);
    asm volatile("ldmatrix.sync.aligned.m8n8.x4.shared.b16 {%0,%1,%2,%3}, [%4];"
                 : "=r"(r[0]), "=r"(r[1]), "=r"(r[2]), "=r"(r[3]) : "r"(a));
}
__device__ __forceinline__ void mma16816(float* c, const unsigned int* a,
                                         const unsigned int* b) {
    asm volatile(
        "mma.sync.aligned.m16n8k16.row.col.f32.bf16.bf16.f32 "
        "{%0,%1,%2,%3}, {%4,%5,%6,%7}, {%8,%9}, {%0,%1,%2,%3};"
        : "+f"(c[0]), "+f"(c[1]), "+f"(c[2]), "+f"(c[3])
        : "r"(a[0]), "r"(a[1]), "r"(a[2]), "r"(a[3]), "r"(b[0]), "r"(b[1]));
}

__global__ void __launch_bounds__(256) gemm_tc(
    const float* __restrict__ A, int lda,
    const float* __restrict__ W, int ldb,
    float* __restrict__ C, int ldc,
    int M, int N, int K,
    const float* __restrict__ bias, int mode,
    const float* __restrict__ e1, int lde1,
    const float* __restrict__ e2, int lde2)
{
    __shared__ __align__(16) __nv_bfloat16 sAhi[128 * SSTR];
    __shared__ __align__(16) __nv_bfloat16 sAlo[128 * SSTR];
    __shared__ __align__(16) __nv_bfloat16 sBhi[64 * SSTR];
    __shared__ __align__(16) __nv_bfloat16 sBlo[64 * SSTR];

    const int tid  = threadIdx.x;
    const int wid  = tid >> 5;
    const int lane = tid & 31;
    const int wm   = wid & 3;          // 0..3  (m)
    const int wn   = wid >> 2;         // 0..1  (n)
    const int m0   = blockIdx.y * 128;
    const int n0   = blockIdx.x * 64;

    // A staging: thread -> row tid/2 (0..127), col (tid&1)*8, 8 floats
    const int ar = tid >> 1;
    const int ac = (tid & 1) * 8;
    // B staging: thread -> row tid/4 (0..63), col (tid&3)*4, 4 floats
    const int br = tid >> 2;
    const int bc = (tid & 3) * 4;
    const bool bvalid = (n0 + br) < N;

    float acc[2][4][4];
    #pragma unroll
    for (int i = 0; i < 2; i++)
        #pragma unroll
        for (int j = 0; j < 4; j++)
            #pragma unroll
            for (int r = 0; r < 4; r++) acc[i][j][r] = 0.0f;

    // fragment ldmatrix source offsets (fixed per thread)
    const int aoff  = (wm * 32 + (lane & 15)) * SSTR + (lane >> 4) * 8;
    const int boff  = (wn * 32 + ((lane >> 4) << 3) + (lane & 7)) * SSTR
                    + ((lane >> 3) & 1) * 8;

    for (int k0 = 0; k0 < K; k0 += 16) {
        // ---- load + split A tile [128x16] ----
        {
            const float* ap = A + (size_t)(m0 + ar) * lda + k0 + ac;
            float4 v0 = *(const float4*)ap;
            float4 v1 = *(const float4*)(ap + 4);
            float va[8];
            va[0]=v0.x; va[1]=v0.y; va[2]=v0.z; va[3]=v0.w;
            va[4]=v1.x; va[5]=v1.y; va[6]=v1.z; va[7]=v1.w;
            __nv_bfloat16* dh = &sAhi[ar * SSTR + ac];
            __nv_bfloat16* dl = &sAlo[ar * SSTR + ac];
            #pragma unroll
            for (int i = 0; i < 8; i++) {
                __nv_bfloat16 hi = __float2bfloat16(va[i]);
                dh[i] = hi;
                dl[i] = __float2bfloat16(va[i] - __bfloat162float(hi));
            }
        }
        // ---- load + split B tile [64x16] ----
        {
            float4 bv = bvalid ? *(const float4*)(W + (size_t)(n0 + br) * ldb + k0 + bc)
                               : make_float4(0.f, 0.f, 0.f, 0.f);
            float vb[4];
            vb[0]=bv.x; vb[1]=bv.y; vb[2]=bv.z; vb[3]=bv.w;
            __nv_bfloat16* dh = &sBhi[br * SSTR + bc];
            __nv_bfloat16* dl = &sBlo[br * SSTR + bc];
            #pragma unroll
            for (int i = 0; i < 4; i++) {
                __nv_bfloat16 hi = __float2bfloat16(vb[i]);
                dh[i] = hi;
                dl[i] = __float2bfloat16(vb[i] - __bfloat162float(hi));
            }
        }
        __syncthreads();

        // ---- fragments (flat arrays, single declarators) ----
        unsigned int ahi[8];
        unsigned int alo[8];
        unsigned int bhi[8];
        unsigned int blo[8];
        ldm_x4(&ahi[0], &sAhi[aoff]);
        ldm_x4(&ahi[4], &sAhi[aoff + 16 * SSTR]);
        ldm_x4(&alo[0], &sAlo[aoff]);
        ldm_x4(&alo[4], &sAlo[aoff + 16 * SSTR]);
        ldm_x4(&bhi[0], &sBhi[boff]);
        ldm_x4(&bhi[4], &sBhi[boff + 16 * SSTR]);
        ldm_x4(&blo[0], &sBlo[boff]);
        ldm_x4(&blo[4], &sBlo[boff + 16 * SSTR]);
        __syncthreads();

        // ---- 3-term split MMA ----
        #pragma unroll
        for (int mi = 0; mi < 2; mi++) {
            #pragma unroll
            for (int ni = 0; ni < 4; ni++) {
                mma16816(acc[mi][ni], &ahi[mi * 4], &bhi[ni * 2]);
                mma16816(acc[mi][ni], &alo[mi * 4], &bhi[ni * 2]);
                mma16816(acc[mi][ni], &ahi[mi * 4], &blo[ni * 2]);
            }
        }
    }

    // ---- epilogue ----
    #pragma unroll
    for (int mi = 0; mi < 2; mi++) {
        #pragma unroll
        for (int ni = 0; ni < 4; ni++) {
            int mb = m0 + wm * 32 + mi * 16 + (lane >> 2);
            int nb = n0 + wn * 32 + ni * 8 + (lane & 3) * 2;
            #pragma unroll
            for (int r = 0; r < 4; r++) {
                int m = mb + ((r >> 1) << 3);
                int n = nb + (r & 1);
                if (n >= N) continue;
                float v = acc[mi][ni][r];
                if (mode == 1)      v += bias[n];
                else if (mode == 2) v = siluf_(v);
                else if (mode == 3) v = sigmoidf_(v) * e1[(size_t)m * lde1 + n]
                                                     * siluf_(e2[(size_t)m * lde2 + n]);
                else if (mode == 4) v += e1[(size_t)m * lde1 + n];
                C[(size_t)m * ldc + n] = v;
            }
        }
    }
}

// ---------------- downsample by 2 (mean of pairs) ----------------
__global__ void down2(const float* __restrict__ src, int lds,
                      float* __restrict__ dst, int Tout)
{
    int idx = blockIdx.x * blockDim.x + threadIdx.x;
    int total = NB * Tout * DIN;
    if (idx >= total) return;
    int d = idx & (DIN - 1);
    int t = (idx >> 10) % Tout;
    int b = idx / (Tout * DIN);
    const float* p = src + (size_t)(b * 2 * Tout + 2 * t) * lds + d;
    dst[idx] = 0.5f * (p[0] + p[lds]);
}

// ---------------- depthwise causal conv (K=4) + bias + SiLU ----------------
__global__ void conv_silu(const float* __restrict__ xin, int ldx,
                          const float* __restrict__ w,
                          const float* __restrict__ bias,
                          float* __restrict__ xc, int Tl)
{
    int idx = blockIdx.x * blockDim.x + threadIdx.x;
    int total = NB * Tl * DIN;
    if (idx >= total) return;
    int d = idx & (DIN - 1);
    int t = (idx >> 10) % Tl;
    int b = idx / (Tl * DIN);
    const float* base = xin + (size_t)(b * Tl) * ldx + d;
    float acc = bias[d];
    #pragma unroll
    for (int k = 0; k < 4; k++) {
        int tt = t + k - 3;
        if (tt >= 0) acc = fmaf(w[d * 4 + k], base[(size_t)tt * ldx], acc);
    }
    xc[idx] = siluf_(acc);
}

// ---------------- selective scan ----------------
__global__ void scan_kernel(const float* __restrict__ xc,
                            const float* __restrict__ proj,
                            const float* __restrict__ dt,
                            const float* __restrict__ A_log,
                            const float* __restrict__ Dp,
                            float* __restrict__ y, int Tl)
{
    const int j    = threadIdx.x & 15;
    const int dloc = threadIdx.x >> 4;
    const int b    = blockIdx.x >> 6;
    const int d0   = (blockIdx.x & 63) * 16;
    const int d    = d0 + dloc;

    __shared__ float s_dt[64][16];
    __shared__ float s_xc[64][16];
    __shared__ float s_B [64][17];
    __shared__ float s_C [64][17];

    const float Aj = -expf(A_log[d * 16 + j]);
    const float Dv = Dp[d];
    float h = 0.0f;

    for (int t0 = 0; t0 < Tl; t0 += 64) {
        for (int i = threadIdx.x; i < 64 * 16; i += 256) {
            int tt = i >> 4, dl = i & 15;
            int gt = t0 + tt;
            size_t rbase = (size_t)(b * Tl + gt);
            s_dt[tt][dl] = softplusf_(dt[rbase * DIN + d0 + dl]);
            s_xc[tt][dl] = xc[rbase * DIN + d0 + dl];
            const float* pr = proj + rbase * NPROJ;
            s_B[tt][dl] = pr[DTRANK + dl];
            s_C[tt][dl] = pr[DTRANK + DSTATE + dl];
        }
        __syncthreads();
        #pragma unroll 4
        for (int tt = 0; tt < 64; tt++) {
            float dtv = s_dt[tt][dloc];
            float xcv = s_xc[tt][dloc];
            float dA  = fmaxf(fexp(dtv * Aj), 1e-38f);
            float dBx = fmaxf(dtv * s_B[tt][j] * xcv, 1e-38f);
            h = fmaf(dA, h, dBx);
            float part = s_C[tt][j] * h;
            part += __shfl_xor_sync(0xffffffffu, part, 8);
            part += __shfl_xor_sync(0xffffffffu, part, 4);
            part += __shfl_xor_sync(0xffffffffu, part, 2);
            part += __shfl_xor_sync(0xffffffffu, part, 1);
            if (j == 0)
                y[(size_t)(b * Tl + t0 + tt) * DIN + d] = fmaf(Dv, xcv, part);
        }
        __syncthreads();
    }
}

// ---------------- softmax of the 3 scale weights ----------------
__global__ void compute_w(const float* __restrict__ sw, float* __restrict__ gw)
{
    float a = sw[0], b = sw[1], c = sw[2];
    float m = fmaxf(a, fmaxf(b, c));
    float ea = expf(a - m), eb = expf(b - m), ec = expf(c - m);
    float s = ea + eb + ec;
    gw[0] = ea / s; gw[1] = eb / s; gw[2] = ec / s;
}

// ---------------- fuse ----------------
__global__ void fuse_kernel(const float* __restrict__ y0,
                            const float* __restrict__ y1,
                            const float* __restrict__ y2,
                            const float* __restrict__ gw,
                            float* __restrict__ fused,
                            float* __restrict__ ctx)
{
    int idx = blockIdx.x * blockDim.x + threadIdx.x;
    int d = idx & (DIN - 1);
    int t = (idx >> 10) & (TLEN - 1);
    int b = idx >> 20;
    float o0 = y0[idx];
    float o1 = y1[(size_t)(b * (TLEN/2) + (t >> 1)) * DIN + d];
    float o2 = y2[(size_t)(b * (TLEN/4) + (t >> 2)) * DIN + d];
    float w0 = gw[0], w1 = gw[1], w2 = gw[2];
    fused[idx] = w0 * o0 + w1 * o1 + w2 * o2;
    ctx[idx]   = (o0 + o1 + o2) * (1.0f / 3.0f);
}

// ---------------- LayerNorm over last dim (512) ----------------
__global__ void ln_kernel(const float* __restrict__ pre,
                          const float* __restrict__ gamma,
                          const float* __restrict__ beta,
                          float* __restrict__ out)
{
    int row = blockIdx.x;
    int tid = threadIdx.x;
    const float* r = pre + (size_t)row * DMODEL;
    float v1 = r[tid], v2 = r[tid + 256];
    float s  = v1 + v2;
    float q  = v1 * v1 + v2 * v2;
    #pragma unroll
    for (int o = 16; o > 0; o >>= 1) {
        s += __shfl_xor_sync(0xffffffffu, s, o);
        q += __shfl_xor_sync(0xffffffffu, q, o);
    }
    __shared__ float sh[8], sh2[8];
    int wid = tid >> 5, lane = tid & 31;
    if (lane == 0) { sh[wid] = s; sh2[wid] = q; }
    __syncthreads();
    if (tid == 0) {
        float ts = 0.f, tq = 0.f;
        #pragma unroll
        for (int i = 0; i < 8; i++) { ts += sh[i]; tq += sh2[i]; }
        sh[0] = ts; sh2[0] = tq;
    }
    __syncthreads();
    float mu  = sh[0] * (1.0f / DMODEL);
    float var = sh2[0] * (1.0f / DMODEL) - mu * mu;
    float inv = rsqrtf(var + 1e-5f);
    float* o = out + (size_t)row * DMODEL;
    o[tid]       = (v1 - mu) * inv * gamma[tid]       + beta[tid];
    o[tid + 256] = (v2 - mu) * inv * gamma[tid + 256] + beta[tid + 256];
}

// ---------------- driver ----------------
extern "C" void kernel_launch(void* const* d_in, const int* in_sizes, int n_in,
                              void* d_out, int out_size)
{
    const float* x        = (const float*)d_in[0];
    const float* in_proj  = (const float*)d_in[1];
    const float* conv_w   = (const float*)d_in[2];
    const float* conv_b   = (const float*)d_in[3];
    const float* xproj_w  = (const float*)d_in[4];
    const float* dtproj_w = (const float*)d_in[5];
    const float* dtproj_b = (const float*)d_in[6];
    const float* A_log    = (const float*)d_in[7];
    const float* D_p      = (const float*)d_in[8];
    const float* sw       = (const float*)d_in[9];
    const float* cg_w1    = (const float*)d_in[10];
    const float* cg_w2    = (const float*)d_in[11];
    const float* out_w    = (const float*)d_in[12];
    const float* ln_g     = (const float*)d_in[13];
    const float* ln_b     = (const float*)d_in[14];
    float* out            = (float*)d_out;

    float *xz, *xs1, *xs2, *xc0, *xc1, *xc2, *p0, *p1, *p2;
    float *dt0, *dt1, *dt2, *y0, *y1, *y2, *fused, *ctx, *h1, *act, *pre, *gw;
    cudaGetSymbolAddress((void**)&xz,   g_xz);
    cudaGetSymbolAddress((void**)&xs1,  g_xs1);
    cudaGetSymbolAddress((void**)&xs2,  g_xs2);
    cudaGetSymbolAddress((void**)&xc0,  g_xc0);
    cudaGetSymbolAddress((void**)&xc1,  g_xc1);
    cudaGetSymbolAddress((void**)&xc2,  g_xc2);
    cudaGetSymbolAddress((void**)&p0,   g_proj0);
    cudaGetSymbolAddress((void**)&p1,   g_proj1);
    cudaGetSymbolAddress((void**)&p2,   g_proj2);
    cudaGetSymbolAddress((void**)&dt0,  g_dt0);
    cudaGetSymbolAddress((void**)&dt1,  g_dt1);
    cudaGetSymbolAddress((void**)&dt2,  g_dt2);
    cudaGetSymbolAddress((void**)&y0,   g_y0);
    cudaGetSymbolAddress((void**)&y1,   g_y1);
    cudaGetSymbolAddress((void**)&y2,   g_y2);
    cudaGetSymbolAddress((void**)&fused,g_fused);
    cudaGetSymbolAddress((void**)&ctx,  g_ctx);
    cudaGetSymbolAddress((void**)&h1,   g_h1);
    cudaGetSymbolAddress((void**)&act,  g_act);
    cudaGetSymbolAddress((void**)&pre,  g_pre);
    cudaGetSymbolAddress((void**)&gw,   g_w);

    // 1. in_proj: xz[2048,2048] = x @ in_proj_w.T
    gemm_tc<<<dim3(32, 16), 256>>>(x, DMODEL, in_proj, DMODEL, xz, 2*DIN,
                                   R0, 2*DIN, DMODEL, nullptr, 0, nullptr, 0, nullptr, 0);

    // 2. downsample
    down2<<<(R1*DIN)/256, 256>>>(xz, 2*DIN, xs1, TLEN/2);
    down2<<<(R2*DIN)/256, 256>>>(xs1, DIN, xs2, TLEN/4);

    // 3. depthwise conv + SiLU
    conv_silu<<<(R0*DIN)/256, 256>>>(xz,  2*DIN, conv_w,          conv_b,          xc0, TLEN);
    conv_silu<<<(R1*DIN)/256, 256>>>(xs1, DIN,   conv_w + 4096,   conv_b + 1024,   xc1, TLEN/2);
    conv_silu<<<(R2*DIN)/256, 256>>>(xs2, DIN,   conv_w + 8192,   conv_b + 2048,   xc2, TLEN/4);

    // 4. xproj (N=96)
    gemm_tc<<<dim3(2, 16), 256>>>(xc0, DIN, xproj_w,          DIN, p0, NPROJ, R0, NPROJ, DIN, nullptr, 0, nullptr, 0, nullptr, 0);
    gemm_tc<<<dim3(2,  8), 256>>>(xc1, DIN, xproj_w +  98304, DIN, p1, NPROJ, R1, NPROJ, DIN, nullptr, 0, nullptr, 0, nullptr, 0);
    gemm_tc<<<dim3(2,  4), 256>>>(xc2, DIN, xproj_w + 196608, DIN, p2, NPROJ, R2, NPROJ, DIN, nullptr, 0, nullptr, 0, nullptr, 0);

    // 5. dtproj (K=64) + bias
    gemm_tc<<<dim3(16, 16), 256>>>(p0, NPROJ, dtproj_w,          DTRANK, dt0, DIN, R0, DIN, DTRANK, dtproj_b,        1, nullptr, 0, nullptr, 0);
    gemm_tc<<<dim3(16,  8), 256>>>(p1, NPROJ, dtproj_w +  65536, DTRANK, dt1, DIN, R1, DIN, DTRANK, dtproj_b + 1024, 1, nullptr, 0, nullptr, 0);
    gemm_tc<<<dim3(16,  4), 256>>>(p2, NPROJ, dtproj_w + 131072, DTRANK, dt2, DIN, R2, DIN, DTRANK, dtproj_b + 2048, 1, nullptr, 0, nullptr, 0);

    // 6. selective scan
    scan_kernel<<<128, 256>>>(xc0, p0, dt0, A_log,         D_p,        y0, TLEN);
    scan_kernel<<<128, 256>>>(xc1, p1, dt1, A_log + 16384, D_p + 1024, y1, TLEN/2);
    scan_kernel<<<128, 256>>>(xc2, p2, dt2, A_log + 32768, D_p + 2048, y2, TLEN/4);

    // 7. fuse
    compute_w<<<1, 1>>>(sw, gw);
    fuse_kernel<<<(R0*DIN)/256, 256>>>(y0, y1, y2, gw, fused, ctx);

    // 8. context gate
    gemm_tc<<<dim3(8, 16), 256>>>(ctx, DIN, cg_w1, DIN, h1, DIN/2, R0, DIN/2, DIN,
                                  nullptr, 2, nullptr, 0, nullptr, 0);
    gemm_tc<<<dim3(16, 16), 256>>>(h1, DIN/2, cg_w2, DIN/2, act, DIN, R0, DIN, DIN/2,
                                   nullptr, 3, fused, DIN, xz + DIN, 2*DIN);

    // 9. out_proj + residual
    gemm_tc<<<dim3(8, 16), 256>>>(act, DIN, out_w, DIN, pre, DMODEL, R0, DMODEL, DIN,
                                  nullptr, 4, x, DMODEL, nullptr, 0);

    // 10. LayerNorm
    ln_kernel<<<R0, 256>>>(pre, ln_g, ln_b, out);
}

// round 4
// speedup vs baseline: 1.8080x; 1.4731x over previous
#include <cuda_runtime.h>
#include <cuda_bf16.h>
#include <stdint.h>
#include <math.h>

// ---------------- problem constants ----------------
#define NB      2
#define TLEN    1024
#define DMODEL  512
#define DIN     1024
#define DTRANK  64
#define DSTATE  16
#define NPROJ   96

#define R0 2048
#define R1 1024
#define R2 512
#define RSUM (R0+R1+R2)

// ---------------- fp32 scratch ----------------
__device__ float g_xz   [R0*2*DIN];
__device__ float g_xs1  [R1*DIN];
__device__ float g_xs2  [R2*DIN];
__device__ float g_xc   [RSUM*DIN];
__device__ float g_proj [RSUM*NPROJ];
__device__ float g_dt   [RSUM*DIN];
__device__ float g_y    [RSUM*DIN];
__device__ float g_fused[R0*DIN];
__device__ float g_pre  [R0*DMODEL];
__device__ float g_w    [4];

// ---------------- bf16 hi/lo planes ----------------
__device__ __nv_bfloat16 g_xh [R0*DMODEL],     g_xl [R0*DMODEL];
__device__ __nv_bfloat16 g_wih[2*DIN*DMODEL],  g_wil[2*DIN*DMODEL];
__device__ __nv_bfloat16 g_xph[3*NPROJ*DIN],   g_xpl[3*NPROJ*DIN];
__device__ __nv_bfloat16 g_dwh[3*DIN*DTRANK],  g_dwl[3*DIN*DTRANK];
__device__ __nv_bfloat16 g_c1h[(DIN/2)*DIN],   g_c1l[(DIN/2)*DIN];
__device__ __nv_bfloat16 g_c2h[DIN*(DIN/2)],   g_c2l[DIN*(DIN/2)];
__device__ __nv_bfloat16 g_owh[DMODEL*DIN],    g_owl[DMODEL*DIN];
__device__ __nv_bfloat16 g_xcH[RSUM*DIN],      g_xcL[RSUM*DIN];
__device__ __nv_bfloat16 g_pH [RSUM*NPROJ],    g_pL [RSUM*NPROJ];
__device__ __nv_bfloat16 g_cth[R0*DIN],        g_ctl[R0*DIN];
__device__ __nv_bfloat16 g_h1h[R0*(DIN/2)],    g_h1l[R0*(DIN/2)];
__device__ __nv_bfloat16 g_ach[R0*DIN],        g_acl[R0*DIN];

// ---------------- math helpers ----------------
__device__ __forceinline__ float fexp(float x) {
    float t = x * 1.4426950408889634f;
    t = fminf(fmaxf(t, -126.0f), 126.0f);
    float fi = rintf(t);
    float f  = t - fi;
    float p  = 1.5403530393e-4f;
    p = fmaf(p, f, 1.3333558146e-3f);
    p = fmaf(p, f, 9.6181291076e-3f);
    p = fmaf(p, f, 5.5504108664e-2f);
    p = fmaf(p, f, 2.4022650695e-1f);
    p = fmaf(p, f, 6.9314718056e-1f);
    p = fmaf(p, f, 1.0f);
    float sc = __int_as_float(((int)fi + 127) << 23);
    return sc * p;
}
__device__ __forceinline__ float sigmoidf_(float x) {
    return __fdividef(1.0f, 1.0f + fexp(-x));
}
__device__ __forceinline__ float siluf_(float x) { return x * sigmoidf_(x); }
__device__ __forceinline__ float softplusf_(float x) {
    return fmaxf(x, 0.0f) + log1pf(fexp(-fabsf(x)));
}
__device__ __forceinline__ void split2(float v, __nv_bfloat16* h, __nv_bfloat16* l) {
    __nv_bfloat16 hi = __float2bfloat16(v);
    *h = hi;
    *l = __float2bfloat16(v - __bfloat162float(hi));
}

// ---------------- split all inputs/weights into bf16 planes ----------------
#define SEG0 (R0*DMODEL)
#define SEG1 (2*DIN*DMODEL)
#define SEG2 (3*NPROJ*DIN)
#define SEG3 (3*DIN*DTRANK)
#define SEG4 ((DIN/2)*DIN)
#define SEG5 (DIN*(DIN/2))
#define SEG6 (DMODEL*DIN)
#define CU0 (SEG0)
#define CU1 (CU0+SEG1)
#define CU2 (CU1+SEG2)
#define CU3 (CU2+SEG3)
#define CU4 (CU3+SEG4)
#define CU5 (CU4+SEG5)
#define CU6 (CU5+SEG6)   // 4161536 total

__global__ void split_all(const float* __restrict__ x,
                          const float* __restrict__ w1,
                          const float* __restrict__ w2,
                          const float* __restrict__ w3,
                          const float* __restrict__ w4,
                          const float* __restrict__ w5,
                          const float* __restrict__ w6)
{
    long i = ((long)blockIdx.x * blockDim.x + threadIdx.x) * 4;
    if (i >= CU6) return;
    const float* src; __nv_bfloat16 *dh, *dl; long off;
    if      (i < CU0) { src=x;  dh=g_xh;  dl=g_xl;  off=0;   }
    else if (i < CU1) { src=w1; dh=g_wih; dl=g_wil; off=CU0; }
    else if (i < CU2) { src=w2; dh=g_xph; dl=g_xpl; off=CU1; }
    else if (i < CU3) { src=w3; dh=g_dwh; dl=g_dwl; off=CU2; }
    else if (i < CU4) { src=w4; dh=g_c1h; dl=g_c1l; off=CU3; }
    else if (i < CU5) { src=w5; dh=g_c2h; dl=g_c2l; off=CU4; }
    else              { src=w6; dh=g_owh; dl=g_owl; off=CU5; }
    long j = i - off;
    float4 v = *(const float4*)(src + j);
    split2(v.x, dh+j,   dl+j);
    split2(v.y, dh+j+1, dl+j+1);
    split2(v.z, dh+j+2, dl+j+2);
    split2(v.w, dh+j+3, dl+j+3);
}

// ---------------- pipelined tensor-core GEMM (pre-split bf16 planes) ----------------
// C[m,n] = epi( sum_k A[m,k]*W[n,k] ), 3-term split: Ah*Wh + Al*Wh + Ah*Wl.
// BM=128, BN=64, BK=32, 256 thr = 8 warps. cp.async double buffer.
#define ASTR 40                 // smem row stride (bf16)
#define APL (128*ASTR)          // A plane elems
#define BPL (64*ASTR)           // B plane elems
#define STG (2*APL + 2*BPL)     // stage elems = 15360
#define SMEM_BYTES (2*STG*2)    // 61440

__device__ __forceinline__ void ldm_x4(unsigned int* r, const __nv_bfloat16* p) {
    unsigned int a = (unsigned int)__cvta_generic_to_shared(p);
    asm volatile("ldmatrix.sync.aligned.m8n8.x4.shared.b16 {%0,%1,%2,%3}, [%4];"
                 : "=r"(r[0]), "=r"(r[1]), "=r"(r[2]), "=r"(r[3]) : "r"(a));
}
__device__ __forceinline__ void mma16816(float* c, const unsigned int* a,
                                         const unsigned int* b) {
    asm volatile(
        "mma.sync.aligned.m16n8k16.row.col.f32.bf16.bf16.f32 "
        "{%0,%1,%2,%3}, {%4,%5,%6,%7}, {%8,%9}, {%0,%1,%2,%3};"
        : "+f"(c[0]), "+f"(c[1]), "+f"(c[2]), "+f"(c[3])
        : "r"(a[0]), "r"(a[1]), "r"(a[2]), "r"(a[3]), "r"(b[0]), "r"(b[1]));
}
__device__ __forceinline__ void cp16(unsigned int dst, const void* src, bool pred) {
    int sz = pred ? 16 : 0;
    asm volatile("cp.async.cg.shared.global [%0], [%1], 16, %2;\n"
                 :: "r"(dst), "l"(src), "r"(sz));
}

__global__ void __launch_bounds__(256) gemm_bf16(
    const __nv_bfloat16* __restrict__ Ahi, const __nv_bfloat16* __restrict__ Alo, int lda,
    const __nv_bfloat16* __restrict__ Whi, const __nv_bfloat16* __restrict__ Wlo, int ldb,
    int wstride,
    float* Cf, __nv_bfloat16* Chi, __nv_bfloat16* Clo, int ldc,
    int4 Ms, int4 rowoffs, int N, int K,
    const float* bias, int bstride, int mode,
    const float* e1, int lde1, const float* e2, int lde2)
{
    extern __shared__ __align__(16) __nv_bfloat16 sm[];
    const int z = blockIdx.z;
    const int M      = (z == 0) ? Ms.x      : ((z == 1) ? Ms.y      : Ms.z);
    const int rowoff = (z == 0) ? rowoffs.x : ((z == 1) ? rowoffs.y : rowoffs.z);
    const int m0 = blockIdx.y * 128;
    if (m0 >= M) return;
    const int n0 = blockIdx.x * 64;

    const int tid = threadIdx.x, lane = tid & 31, wid = tid >> 5;
    const int wm = wid & 3, wn = wid >> 2;

    const __nv_bfloat16* Ah = Ahi + (size_t)rowoff * lda;
    const __nv_bfloat16* Al = Alo + (size_t)rowoff * lda;
    const __nv_bfloat16* Wh = Whi + (size_t)z * wstride;
    const __nv_bfloat16* Wl = Wlo + (size_t)z * wstride;

    const int arow = tid >> 1, acol = (tid & 1) * 16;
    const int brow = tid >> 2, bcol = (tid & 3) * 8;
    const bool bv = (n0 + brow) < N;

    const __nv_bfloat16* agh = Ah + (size_t)(m0 + arow) * lda + acol;
    const __nv_bfloat16* agl = Al + (size_t)(m0 + arow) * lda + acol;
    const __nv_bfloat16* bgh = Wh + (size_t)(n0 + brow) * ldb + bcol;
    const __nv_bfloat16* bgl = Wl + (size_t)(n0 + brow) * ldb + bcol;

    unsigned int sbase = (unsigned int)__cvta_generic_to_shared(sm);
    const int a_dst = arow * ASTR + acol;
    const int b_dst = brow * ASTR + bcol;

    float acc[2][4][4];
    #pragma unroll
    for (int i = 0; i < 2; i++)
        #pragma unroll
        for (int j = 0; j < 4; j++)
            #pragma unroll
            for (int r = 0; r < 4; r++) acc[i][j][r] = 0.0f;

    const int aoff = (wm * 32 + (lane & 15)) * ASTR + (lane >> 4) * 8;
    const int boff = (wn * 32 + ((lane >> 4) << 3) + (lane & 7)) * ASTR
                   + ((lane >> 3) & 1) * 8;

    const int nk = K / 32;

    // prologue: stage 0
    {
        unsigned int st = sbase;
        cp16(st + (a_dst) * 2,                 agh,       true);
        cp16(st + (a_dst + 8) * 2,             agh + 8,   true);
        cp16(st + (APL + a_dst) * 2,           agl,       true);
        cp16(st + (APL + a_dst + 8) * 2,       agl + 8,   true);
        cp16(st + (2 * APL + b_dst) * 2,       bgh,       bv);
        cp16(st + (2 * APL + BPL + b_dst) * 2, bgl,       bv);
        asm volatile("cp.async.commit_group;\n");
    }

    for (int it = 0; it < nk; it++) {
        if (it + 1 < nk) {
            int k0 = (it + 1) * 32;
            unsigned int st = sbase + ((it + 1) & 1) * STG * 2;
            cp16(st + (a_dst) * 2,                 agh + k0,     true);
            cp16(st + (a_dst + 8) * 2,             agh + k0 + 8, true);
            cp16(st + (APL + a_dst) * 2,           agl + k0,     true);
            cp16(st + (APL + a_dst + 8) * 2,       agl + k0 + 8, true);
            cp16(st + (2 * APL + b_dst) * 2,       bgh + k0,     bv);
            cp16(st + (2 * APL + BPL + b_dst) * 2, bgl + k0,     bv);
            asm volatile("cp.async.commit_group;\n");
            asm volatile("cp.async.wait_group 1;\n");
        } else {
            asm volatile("cp.async.wait_group 0;\n");
        }
        __syncthreads();

        const __nv_bfloat16* st = sm + (it & 1) * STG;
        #pragma unroll
        for (int k16 = 0; k16 < 2; k16++) {
            unsigned int ahif[8];
            unsigned int alof[8];
            unsigned int bhif[8];
            unsigned int blof[8];
            const __nv_bfloat16* pa = st + aoff + k16 * 16;
            ldm_x4(&ahif[0], pa);
            ldm_x4(&ahif[4], pa + 16 * ASTR);
            ldm_x4(&alof[0], pa + APL);
            ldm_x4(&alof[4], pa + APL + 16 * ASTR);
            const __nv_bfloat16* pb = st + 2 * APL + boff + k16 * 16;
            ldm_x4(&bhif[0], pb);
            ldm_x4(&bhif[4], pb + 16 * ASTR);
            ldm_x4(&blof[0], pb + BPL);
            ldm_x4(&blof[4], pb + BPL + 16 * ASTR);
            #pragma unroll
            for (int mi = 0; mi < 2; mi++) {
                #pragma unroll
                for (int ni = 0; ni < 4; ni++) {
                    mma16816(acc[mi][ni], &ahif[mi * 4], &bhif[ni * 2]);
                    mma16816(acc[mi][ni], &alof[mi * 4], &bhif[ni * 2]);
                    mma16816(acc[mi][ni], &ahif[mi * 4], &blof[ni * 2]);
                }
            }
        }
        __syncthreads();
    }

    // ---- epilogue ----
    #pragma unroll
    for (int mi = 0; mi < 2; mi++) {
        #pragma unroll
        for (int ni = 0; ni < 4; ni++) {
            int mb = m0 + wm * 32 + mi * 16 + (lane >> 2);
            int nb = n0 + wn * 32 + ni * 8 + (lane & 3) * 2;
            #pragma unroll
            for (int r = 0; r < 4; r++) {
                int mloc = mb + ((r >> 1) << 3);
                int n = nb + (r & 1);
                if (n >= N) continue;
                int m = rowoff + mloc;
                float v = acc[mi][ni][r];
                if (mode == 1)      v += bias[z * bstride + n];
                else if (mode == 2) v = siluf_(v);
                else if (mode == 3) v = sigmoidf_(v) * e1[(size_t)m * lde1 + n]
                                                     * siluf_(e2[(size_t)m * lde2 + n]);
                else if (mode == 4) v += e1[(size_t)m * lde1 + n];
                size_t o = (size_t)m * ldc + n;
                if (Cf)  Cf[o] = v;
                if (Chi) split2(v, Chi + o, Clo + o);
            }
        }
    }
}

// ---------------- downsample by 2 ----------------
__global__ void down2(const float* __restrict__ src, int lds,
                      float* __restrict__ dst, int Tout)
{
    int idx = blockIdx.x * blockDim.x + threadIdx.x;
    int total = NB * Tout * DIN;
    if (idx >= total) return;
    int d = idx & (DIN - 1);
    int t = (idx >> 10) % Tout;
    int b = idx / (Tout * DIN);
    const float* p = src + (size_t)(b * 2 * Tout + 2 * t) * lds + d;
    dst[idx] = 0.5f * (p[0] + p[lds]);
}

// ---------------- depthwise causal conv (K=4) + bias + SiLU, batched over scales ----------------
__global__ void conv_batched(const float* __restrict__ cw,
                             const float* __restrict__ cb)
{
    int z = blockIdx.y;
    int Tl = TLEN >> z;
    int total = NB * Tl * DIN;
    int idx = blockIdx.x * blockDim.x + threadIdx.x;
    if (idx >= total) return;
    const float* xin = (z == 0) ? g_xz : ((z == 1) ? g_xs1 : g_xs2);
    int ldx = (z == 0) ? 2 * DIN : DIN;
    size_t roff = (z == 0) ? 0 : ((z == 1) ? (size_t)R0 * DIN : (size_t)(R0 + R1) * DIN);
    const float* w = cw + z * DIN * 4;
    const float* bias = cb + z * DIN;

    int d = idx & (DIN - 1);
    int t = (idx >> 10) % Tl;
    int b = idx / (Tl * DIN);
    const float* base = xin + (size_t)(b * Tl) * ldx + d;
    float acc = bias[d];
    #pragma unroll
    for (int k = 0; k < 4; k++) {
        int tt = t + k - 3;
        if (tt >= 0) acc = fmaf(w[d * 4 + k], base[(size_t)tt * ldx], acc);
    }
    float v = siluf_(acc);
    g_xc[roff + idx] = v;
    split2(v, g_xcH + roff + idx, g_xcL + roff + idx);
}

// ---------------- selective scan, batched over scales ----------------
__global__ void scan_batched(const float* __restrict__ A_log,
                             const float* __restrict__ Dp)
{
    const int z = blockIdx.y;
    const int Tl = TLEN >> z;
    const size_t roff  = (z == 0) ? 0 : ((z == 1) ? (size_t)R0 : (size_t)(R0 + R1));
    const float* xc   = g_xc   + roff * DIN;
    const float* proj = g_proj + roff * NPROJ;
    const float* dt   = g_dt   + roff * DIN;
    float*       y    = g_y    + roff * DIN;
    const float* Al   = A_log + z * DIN * DSTATE;
    const float* Dz   = Dp + z * DIN;

    const int j    = threadIdx.x & 15;
    const int dloc = threadIdx.x >> 4;
    const int b    = blockIdx.x >> 6;
    const int d0   = (blockIdx.x & 63) * 16;
    const int d    = d0 + dloc;

    __shared__ float s_dt[64][16];
    __shared__ float s_xc[64][16];
    __shared__ float s_B [64][17];
    __shared__ float s_C [64][17];

    const float Aj = -expf(Al[d * 16 + j]);
    const float Dv = Dz[d];
    float h = 0.0f;

    for (int t0 = 0; t0 < Tl; t0 += 64) {
        for (int i = threadIdx.x; i < 64 * 16; i += 256) {
            int tt = i >> 4, dl = i & 15;
            size_t rbase = (size_t)(b * Tl + t0 + tt);
            s_dt[tt][dl] = softplusf_(dt[rbase * DIN + d0 + dl]);
            s_xc[tt][dl] = xc[rbase * DIN + d0 + dl];
            const float* pr = proj + rbase * NPROJ;
            s_B[tt][dl] = pr[DTRANK + dl];
            s_C[tt][dl] = pr[DTRANK + DSTATE + dl];
        }
        __syncthreads();
        #pragma unroll 4
        for (int tt = 0; tt < 64; tt++) {
            float dtv = s_dt[tt][dloc];
            float xcv = s_xc[tt][dloc];
            float dA  = fmaxf(fexp(dtv * Aj), 1e-38f);
            float dBx = fmaxf(dtv * s_B[tt][j] * xcv, 1e-38f);
            h = fmaf(dA, h, dBx);
            float part = s_C[tt][j] * h;
            part += __shfl_xor_sync(0xffffffffu, part, 8);
            part += __shfl_xor_sync(0xffffffffu, part, 4);
            part += __shfl_xor_sync(0xffffffffu, part, 2);
            part += __shfl_xor_sync(0xffffffffu, part, 1);
            if (j == 0)
                y[(size_t)(b * Tl + t0 + tt) * DIN + d] = fmaf(Dv, xcv, part);
        }
        __syncthreads();
    }
}

// ---------------- softmax of scale weights ----------------
__global__ void compute_w(const float* __restrict__ sw)
{
    float a = sw[0], b = sw[1], c = sw[2];
    float m = fmaxf(a, fmaxf(b, c));
    float ea = expf(a - m), eb = expf(b - m), ec = expf(c - m);
    float s = ea + eb + ec;
    g_w[0] = ea / s; g_w[1] = eb / s; g_w[2] = ec / s;
}

// ---------------- fuse: weighted sum + ctx planes ----------------
__global__ void fuse_kernel()
{
    int idx = blockIdx.x * blockDim.x + threadIdx.x;
    int d = idx & (DIN - 1);
    int t = (idx >> 10) & (TLEN - 1);
    int b = idx >> 20;
    float o0 = g_y[idx];
    float o1 = g_y[(size_t)R0 * DIN + (size_t)(b * (TLEN/2) + (t >> 1)) * DIN + d];
    float o2 = g_y[(size_t)(R0 + R1) * DIN + (size_t)(b * (TLEN/4) + (t >> 2)) * DIN + d];
    g_fused[idx] = g_w[0] * o0 + g_w[1] * o1 + g_w[2] * o2;
    float c = (o0 + o1 + o2) * (1.0f / 3.0f);
    split2(c, g_cth + idx, g_ctl + idx);
}

// ---------------- LayerNorm ----------------
__global__ void ln_kernel(const float* __restrict__ gamma,
                          const float* __restrict__ beta,
                          float* __restrict__ out)
{
    int row = blockIdx.x;
    int tid = threadIdx.x;
    const float* r = g_pre + (size_t)row * DMODEL;
    float v1 = r[tid], v2 = r[tid + 256];
    float s  = v1 + v2;
    float q  = v1 * v1 + v2 * v2;
    #pragma unroll
    for (int o = 16; o > 0; o >>= 1) {
        s += __shfl_xor_sync(0xffffffffu, s, o);
        q += __shfl_xor_sync(0xffffffffu, q, o);
    }
    __shared__ float sh[8], sh2[8];
    int wid = tid >> 5, lane = tid & 31;
    if (lane == 0) { sh[wid] = s; sh2[wid] = q; }
    __syncthreads();
    if (tid == 0) {
        float ts = 0.f, tq = 0.f;
        #pragma unroll
        for (int i = 0; i < 8; i++) { ts += sh[i]; tq += sh2[i]; }
        sh[0] = ts; sh2[0] = tq;
    }
    __syncthreads();
    float mu  = sh[0] * (1.0f / DMODEL);
    float var = sh2[0] * (1.0f / DMODEL) - mu * mu;
    float inv = rsqrtf(var + 1e-5f);
    float* o = out + (size_t)row * DMODEL;
    o[tid]       = (v1 - mu) * inv * gamma[tid]       + beta[tid];
    o[tid + 256] = (v2 - mu) * inv * gamma[tid + 256] + beta[tid + 256];
}

// ---------------- driver ----------------
extern "C" void kernel_launch(void* const* d_in, const int* in_sizes, int n_in,
                              void* d_out, int out_size)
{
    const float* x        = (const float*)d_in[0];
    const float* in_proj  = (const float*)d_in[1];
    const float* conv_w   = (const float*)d_in[2];
    const float* conv_b   = (const float*)d_in[3];
    const float* xproj_w  = (const float*)d_in[4];
    const float* dtproj_w = (const float*)d_in[5];
    const float* dtproj_b = (const float*)d_in[6];
    const float* A_log    = (const float*)d_in[7];
    const float* D_p      = (const float*)d_in[8];
    const float* sw       = (const float*)d_in[9];
    const float* cg_w1    = (const float*)d_in[10];
    const float* cg_w2    = (const float*)d_in[11];
    const float* out_w    = (const float*)d_in[12];
    const float* ln_g     = (const float*)d_in[13];
    const float* ln_b     = (const float*)d_in[14];
    float* out            = (float*)d_out;

    static bool attr_set = false;
    if (!attr_set) {
        cudaFuncSetAttribute(gemm_bf16, cudaFuncAttributeMaxDynamicSharedMemorySize,
                             SMEM_BYTES);
        attr_set = true;
    }

    // symbol addresses
    float *xz, *xs1, *xs2, *proj, *dtb, *fused, *pre;
    __nv_bfloat16 *xh,*xl,*wih,*wil,*xph,*xpl,*dwh,*dwl,*c1h,*c1l,*c2h,*c2l,*owh,*owl;
    __nv_bfloat16 *xcH,*xcL,*pH,*pL,*cth,*ctl,*h1h,*h1l,*ach,*acl;
    cudaGetSymbolAddress((void**)&xz,   g_xz);
    cudaGetSymbolAddress((void**)&xs1,  g_xs1);
    cudaGetSymbolAddress((void**)&xs2,  g_xs2);
    cudaGetSymbolAddress((void**)&proj, g_proj);
    cudaGetSymbolAddress((void**)&dtb,  g_dt);
    cudaGetSymbolAddress((void**)&fused,g_fused);
    cudaGetSymbolAddress((void**)&pre,  g_pre);
    cudaGetSymbolAddress((void**)&xh,  g_xh);   cudaGetSymbolAddress((void**)&xl,  g_xl);
    cudaGetSymbolAddress((void**)&wih, g_wih);  cudaGetSymbolAddress((void**)&wil, g_wil);
    cudaGetSymbolAddress((void**)&xph, g_xph);  cudaGetSymbolAddress((void**)&xpl, g_xpl);
    cudaGetSymbolAddress((void**)&dwh, g_dwh);  cudaGetSymbolAddress((void**)&dwl, g_dwl);
    cudaGetSymbolAddress((void**)&c1h, g_c1h);  cudaGetSymbolAddress((void**)&c1l, g_c1l);
    cudaGetSymbolAddress((void**)&c2h, g_c2h);  cudaGetSymbolAddress((void**)&c2l, g_c2l);
    cudaGetSymbolAddress((void**)&owh, g_owh);  cudaGetSymbolAddress((void**)&owl, g_owl);
    cudaGetSymbolAddress((void**)&xcH, g_xcH);  cudaGetSymbolAddress((void**)&xcL, g_xcL);
    cudaGetSymbolAddress((void**)&pH,  g_pH);   cudaGetSymbolAddress((void**)&pL,  g_pL);
    cudaGetSymbolAddress((void**)&cth, g_cth);  cudaGetSymbolAddress((void**)&ctl, g_ctl);
    cudaGetSymbolAddress((void**)&h1h, g_h1h);  cudaGetSymbolAddress((void**)&h1l, g_h1l);
    cudaGetSymbolAddress((void**)&ach, g_ach);  cudaGetSymbolAddress((void**)&acl, g_acl);

    const int4 M1   = make_int4(R0, 0, 0, 0);
    const int4 OFF0 = make_int4(0, 0, 0, 0);
    const int4 M3   = make_int4(R0, R1, R2, 0);
    const int4 OFF3 = make_int4(0, R0, R0 + R1, 0);

    // 0. split inputs + weights into bf16 planes
    split_all<<<(CU6/4 + 255)/256, 256>>>(x, in_proj, xproj_w, dtproj_w,
                                          cg_w1, cg_w2, out_w);

    // 1. in_proj: xz = x @ in_proj_w.T   [2048 x 2048 x 512]
    gemm_bf16<<<dim3(32, 16, 1), 256, SMEM_BYTES>>>(
        xh, xl, DMODEL, wih, wil, DMODEL, 0,
        xz, nullptr, nullptr, 2*DIN, M1, OFF0, 2*DIN, DMODEL,
        nullptr, 0, 0, nullptr, 0, nullptr, 0);

    // 2. downsample
    down2<<<(R1*DIN)/256, 256>>>(xz, 2*DIN, xs1, TLEN/2);
    down2<<<(R2*DIN)/256, 256>>>(xs1, DIN,  xs2, TLEN/4);

    // 3. conv (batched, writes fp32 + planes)
    conv_batched<<<dim3((R0*DIN)/256, 3), 256>>>(conv_w, conv_b);

    // 4. xproj (batched): proj = xc @ xproj_w[s].T   N=96, K=1024
    gemm_bf16<<<dim3(2, 16, 3), 256, SMEM_BYTES>>>(
        xcH, xcL, DIN, xph, xpl, DIN, NPROJ*DIN,
        proj, pH, pL, NPROJ, M3, OFF3, NPROJ, DIN,
        nullptr, 0, 0, nullptr, 0, nullptr, 0);

    // 5. dtproj (batched): dt = proj[:, :64] @ dtproj_w[s].T + bias   N=1024, K=64
    gemm_bf16<<<dim3(16, 16, 3), 256, SMEM_BYTES>>>(
        pH, pL, NPROJ, dwh, dwl, DTRANK, DIN*DTRANK,
        dtb, nullptr, nullptr, DIN, M3, OFF3, DIN, DTRANK,
        dtproj_b, DIN, 1, nullptr, 0, nullptr, 0);

    // 6. selective scan (batched)
    scan_batched<<<dim3(128, 3), 256>>>(A_log, D_p);

    // 7. fuse
    compute_w<<<1, 1>>>(sw);
    fuse_kernel<<<(R0*DIN)/256, 256>>>();

    // 8. context gate
    gemm_bf16<<<dim3(8, 16, 1), 256, SMEM_BYTES>>>(
        cth, ctl, DIN, c1h, c1l, DIN, 0,
        nullptr, h1h, h1l, DIN/2, M1, OFF0, DIN/2, DIN,
        nullptr, 0, 2, nullptr, 0, nullptr, 0);
    gemm_bf16<<<dim3(16, 16, 1), 256, SMEM_BYTES>>>(
        h1h, h1l, DIN/2, c2h, c2l, DIN/2, 0,
        nullptr, ach, acl, DIN, M1, OFF0, DIN, DIN/2,
        nullptr, 0, 3, fused, DIN, xz + DIN, 2*DIN);

    // 9. out_proj + residual
    gemm_bf16<<<dim3(8, 16, 1), 256, SMEM_BYTES>>>(
        ach, acl, DIN, owh, owl, DIN, 0,
        pre, nullptr, nullptr, DMODEL, M1, OFF0, DMODEL, DIN,
        nullptr, 0, 4, x, DMODEL, nullptr, 0);

    // 10. LayerNorm
    ln_kernel<<<R0, 256>>>(ln_g, ln_b, out);
}

// round 5
// speedup vs baseline: 1.8831x; 1.0416x over previous
#include <cuda_runtime.h>
#include <cuda_bf16.h>
#include <stdint.h>
#include <math.h>

// ---------------- problem constants ----------------
#define NB      2
#define TLEN    1024
#define DMODEL  512
#define DIN     1024
#define DTRANK  64
#define DSTATE  16
#define NPROJ   96

#define R0 2048
#define R1 1024
#define R2 512
#define RSUM (R0+R1+R2)

// ---------------- fp32 scratch ----------------
__device__ float g_xz   [R0*2*DIN];
__device__ float g_xs1  [R1*DIN];
__device__ float g_xs2  [R2*DIN];
__device__ float g_xc   [RSUM*DIN];
__device__ float g_proj [RSUM*NPROJ];
__device__ float g_dt   [RSUM*DIN];
__device__ float g_y    [RSUM*DIN];
__device__ float g_fused[R0*DIN];
__device__ float g_pre  [R0*DMODEL];
__device__ float g_w    [4];

// ---------------- bf16 hi/lo planes ----------------
__device__ __nv_bfloat16 g_xh [R0*DMODEL],     g_xl [R0*DMODEL];
__device__ __nv_bfloat16 g_wih[2*DIN*DMODEL],  g_wil[2*DIN*DMODEL];
__device__ __nv_bfloat16 g_xph[3*NPROJ*DIN],   g_xpl[3*NPROJ*DIN];
__device__ __nv_bfloat16 g_dwh[3*DIN*DTRANK],  g_dwl[3*DIN*DTRANK];
__device__ __nv_bfloat16 g_c1h[(DIN/2)*DIN],   g_c1l[(DIN/2)*DIN];
__device__ __nv_bfloat16 g_c2h[DIN*(DIN/2)],   g_c2l[DIN*(DIN/2)];
__device__ __nv_bfloat16 g_owh[DMODEL*DIN],    g_owl[DMODEL*DIN];
__device__ __nv_bfloat16 g_xcH[RSUM*DIN],      g_xcL[RSUM*DIN];
__device__ __nv_bfloat16 g_pH [RSUM*NPROJ],    g_pL [RSUM*NPROJ];
__device__ __nv_bfloat16 g_cth[R0*DIN],        g_ctl[R0*DIN];
__device__ __nv_bfloat16 g_h1h[R0*(DIN/2)],    g_h1l[R0*(DIN/2)];
__device__ __nv_bfloat16 g_ach[R0*DIN],        g_acl[R0*DIN];

// ---------------- math helpers ----------------
__device__ __forceinline__ float fexp(float x) {
    float t = x * 1.4426950408889634f;
    t = fminf(fmaxf(t, -126.0f), 126.0f);
    float fi = rintf(t);
    float f  = t - fi;
    float p  = 1.5403530393e-4f;
    p = fmaf(p, f, 1.3333558146e-3f);
    p = fmaf(p, f, 9.6181291076e-3f);
    p = fmaf(p, f, 5.5504108664e-2f);
    p = fmaf(p, f, 2.4022650695e-1f);
    p = fmaf(p, f, 6.9314718056e-1f);
    p = fmaf(p, f, 1.0f);
    float sc = __int_as_float(((int)fi + 127) << 23);
    return sc * p;
}
__device__ __forceinline__ float sigmoidf_(float x) {
    return __fdividef(1.0f, 1.0f + fexp(-x));
}
__device__ __forceinline__ float siluf_(float x) { return x * sigmoidf_(x); }
__device__ __forceinline__ float softplusf_(float x) {
    return fmaxf(x, 0.0f) + log1pf(fexp(-fabsf(x)));
}
__device__ __forceinline__ void split2(float v, __nv_bfloat16* h, __nv_bfloat16* l) {
    __nv_bfloat16 hi = __float2bfloat16(v);
    *h = hi;
    *l = __float2bfloat16(v - __bfloat162float(hi));
}

// ---------------- split all inputs/weights into bf16 planes ----------------
#define SEG0 (R0*DMODEL)
#define SEG1 (2*DIN*DMODEL)
#define SEG2 (3*NPROJ*DIN)
#define SEG3 (3*DIN*DTRANK)
#define SEG4 ((DIN/2)*DIN)
#define SEG5 (DIN*(DIN/2))
#define SEG6 (DMODEL*DIN)
#define CU0 (SEG0)
#define CU1 (CU0+SEG1)
#define CU2 (CU1+SEG2)
#define CU3 (CU2+SEG3)
#define CU4 (CU3+SEG4)
#define CU5 (CU4+SEG5)
#define CU6 (CU5+SEG6)

__global__ void split_all(const float* __restrict__ x,
                          const float* __restrict__ w1,
                          const float* __restrict__ w2,
                          const float* __restrict__ w3,
                          const float* __restrict__ w4,
                          const float* __restrict__ w5,
                          const float* __restrict__ w6)
{
    long i = ((long)blockIdx.x * blockDim.x + threadIdx.x) * 4;
    if (i >= CU6) return;
    const float* src; __nv_bfloat16 *dh, *dl; long off;
    if      (i < CU0) { src=x;  dh=g_xh;  dl=g_xl;  off=0;   }
    else if (i < CU1) { src=w1; dh=g_wih; dl=g_wil; off=CU0; }
    else if (i < CU2) { src=w2; dh=g_xph; dl=g_xpl; off=CU1; }
    else if (i < CU3) { src=w3; dh=g_dwh; dl=g_dwl; off=CU2; }
    else if (i < CU4) { src=w4; dh=g_c1h; dl=g_c1l; off=CU3; }
    else if (i < CU5) { src=w5; dh=g_c2h; dl=g_c2l; off=CU4; }
    else              { src=w6; dh=g_owh; dl=g_owl; off=CU5; }
    long j = i - off;
    float4 v = *(const float4*)(src + j);
    split2(v.x, dh+j,   dl+j);
    split2(v.y, dh+j+1, dl+j+1);
    split2(v.z, dh+j+2, dl+j+2);
    split2(v.w, dh+j+3, dl+j+3);
}

// ---------------- 3-stage pipelined tensor-core GEMM (pre-split bf16 planes) ----------------
// C[m,n] = epi( sum_k A[m,k]*W[n,k] ), 3-term split: Ah*Wh + Al*Wh + Ah*Wl.
// BM=128, BN=64, BK=32, 256 thr = 8 warps. Single __syncthreads per k-iter:
// prefetch for stage it+S-1 is issued AFTER the barrier, so overwriting buffer
// (it-1)%S is safe (all threads finished computing it before the barrier).
#define ASTR 40
#define APL (128*ASTR)
#define BPL (64*ASTR)
#define STG (2*APL + 2*BPL)            // 15360 elems per stage
#define NSTAGE 3
#define SMEM_BYTES (NSTAGE*STG*2)      // 92160 B

__device__ __forceinline__ void ldm_x4(unsigned int* r, const __nv_bfloat16* p) {
    unsigned int a = (unsigned int)__cvta_generic_to_shared(p);
    asm volatile("ldmatrix.sync.aligned.m8n8.x4.shared.b16 {%0,%1,%2,%3}, [%4];"
                 : "=r"(r[0]), "=r"(r[1]), "=r"(r[2]), "=r"(r[3]) : "r"(a));
}
__device__ __forceinline__ void mma16816(float* c, const unsigned int* a,
                                         const unsigned int* b) {
    asm volatile(
        "mma.sync.aligned.m16n8k16.row.col.f32.bf16.bf16.f32 "
        "{%0,%1,%2,%3}, {%4,%5,%6,%7}, {%8,%9}, {%0,%1,%2,%3};"
        : "+f"(c[0]), "+f"(c[1]), "+f"(c[2]), "+f"(c[3])
        : "r"(a[0]), "r"(a[1]), "r"(a[2]), "r"(a[3]), "r"(b[0]), "r"(b[1]));
}
__device__ __forceinline__ void cp16(unsigned int dst, const void* src, bool pred) {
    int sz = pred ? 16 : 0;
    asm volatile("cp.async.cg.shared.global [%0], [%1], 16, %2;\n"
                 :: "r"(dst), "l"(src), "r"(sz));
}

__global__ void __launch_bounds__(256, 2) gemm_bf16(
    const __nv_bfloat16* __restrict__ Ahi, const __nv_bfloat16* __restrict__ Alo, int lda,
    const __nv_bfloat16* __restrict__ Whi, const __nv_bfloat16* __restrict__ Wlo, int ldb,
    int wstride,
    float* Cf, __nv_bfloat16* Chi, __nv_bfloat16* Clo, int ldc,
    int4 Ms, int4 rowoffs, int N, int K,
    const float* bias, int bstride, int mode,
    const float* e1, int lde1, const float* e2, int lde2)
{
    extern __shared__ __align__(16) __nv_bfloat16 sm[];
    const int z = blockIdx.z;
    const int M      = (z == 0) ? Ms.x      : ((z == 1) ? Ms.y      : Ms.z);
    const int rowoff = (z == 0) ? rowoffs.x : ((z == 1) ? rowoffs.y : rowoffs.z);
    const int m0 = blockIdx.y * 128;
    if (m0 >= M) return;
    const int n0 = blockIdx.x * 64;

    const int tid = threadIdx.x, lane = tid & 31, wid = tid >> 5;
    const int wm = wid & 3, wn = wid >> 2;

    const __nv_bfloat16* Ah = Ahi + (size_t)rowoff * lda;
    const __nv_bfloat16* Al = Alo + (size_t)rowoff * lda;
    const __nv_bfloat16* Wh = Whi + (size_t)z * wstride;
    const __nv_bfloat16* Wl = Wlo + (size_t)z * wstride;

    const int arow = tid >> 1, acol = (tid & 1) * 16;
    const int brow = tid >> 2, bcol = (tid & 3) * 8;
    const bool bv = (n0 + brow) < N;

    const __nv_bfloat16* agh = Ah + (size_t)(m0 + arow) * lda + acol;
    const __nv_bfloat16* agl = Al + (size_t)(m0 + arow) * lda + acol;
    const __nv_bfloat16* bgh = Wh + (size_t)(n0 + brow) * ldb + bcol;
    const __nv_bfloat16* bgl = Wl + (size_t)(n0 + brow) * ldb + bcol;

    unsigned int sbase = (unsigned int)__cvta_generic_to_shared(sm);
    const int a_dst = arow * ASTR + acol;
    const int b_dst = brow * ASTR + bcol;

    float acc[2][4][4];
    #pragma unroll
    for (int i = 0; i < 2; i++)
        #pragma unroll
        for (int j = 0; j < 4; j++)
            #pragma unroll
            for (int r = 0; r < 4; r++) acc[i][j][r] = 0.0f;

    const int aoff = (wm * 32 + (lane & 15)) * ASTR + (lane >> 4) * 8;
    const int boff = (wn * 32 + ((lane >> 4) << 3) + (lane & 7)) * ASTR
                   + ((lane >> 3) & 1) * 8;

    const int nk = K / 32;

    auto issue = [&](int s) {
        int k0 = s * 32;
        unsigned int st = sbase + (unsigned int)(s % NSTAGE) * (STG * 2);
        cp16(st + (a_dst) * 2,                 agh + k0,     true);
        cp16(st + (a_dst + 8) * 2,             agh + k0 + 8, true);
        cp16(st + (APL + a_dst) * 2,           agl + k0,     true);
        cp16(st + (APL + a_dst + 8) * 2,       agl + k0 + 8, true);
        cp16(st + (2 * APL + b_dst) * 2,       bgh + k0,     bv);
        cp16(st + (2 * APL + BPL + b_dst) * 2, bgl + k0,     bv);
    };

    // prologue: stages 0..NSTAGE-2
    #pragma unroll
    for (int s = 0; s < NSTAGE - 1; s++) {
        if (s < nk) issue(s);
        asm volatile("cp.async.commit_group;\n");
    }

    for (int it = 0; it < nk; it++) {
        asm volatile("cp.async.wait_group %0;\n" :: "n"(NSTAGE - 2));
        __syncthreads();

        // prefetch stage it+NSTAGE-1 (after barrier: safe to overwrite (it-1)%NSTAGE)
        int pf = it + NSTAGE - 1;
        if (pf < nk) issue(pf);
        asm volatile("cp.async.commit_group;\n");

        const __nv_bfloat16* st = sm + (it % NSTAGE) * STG;
        #pragma unroll
        for (int k16 = 0; k16 < 2; k16++) {
            unsigned int ahif[8];
            unsigned int alof[8];
            unsigned int bhif[8];
            unsigned int blof[8];
            const __nv_bfloat16* pa = st + aoff + k16 * 16;
            ldm_x4(&ahif[0], pa);
            ldm_x4(&ahif[4], pa + 16 * ASTR);
            ldm_x4(&alof[0], pa + APL);
            ldm_x4(&alof[4], pa + APL + 16 * ASTR);
            const __nv_bfloat16* pb = st + 2 * APL + boff + k16 * 16;
            ldm_x4(&bhif[0], pb);
            ldm_x4(&bhif[4], pb + 16 * ASTR);
            ldm_x4(&blof[0], pb + BPL);
            ldm_x4(&blof[4], pb + BPL + 16 * ASTR);
            #pragma unroll
            for (int mi = 0; mi < 2; mi++) {
                #pragma unroll
                for (int ni = 0; ni < 4; ni++) {
                    mma16816(acc[mi][ni], &ahif[mi * 4], &bhif[ni * 2]);
                    mma16816(acc[mi][ni], &alof[mi * 4], &bhif[ni * 2]);
                    mma16816(acc[mi][ni], &ahif[mi * 4], &blof[ni * 2]);
                }
            }
        }
    }

    // ---- epilogue ----
    #pragma unroll
    for (int mi = 0; mi < 2; mi++) {
        #pragma unroll
        for (int ni = 0; ni < 4; ni++) {
            int mb = m0 + wm * 32 + mi * 16 + (lane >> 2);
            int nb = n0 + wn * 32 + ni * 8 + (lane & 3) * 2;
            #pragma unroll
            for (int r = 0; r < 4; r++) {
                int mloc = mb + ((r >> 1) << 3);
                int n = nb + (r & 1);
                if (n >= N) continue;
                int m = rowoff + mloc;
                float v = acc[mi][ni][r];
                if (mode == 1)      v += bias[z * bstride + n];
                else if (mode == 2) v = siluf_(v);
                else if (mode == 3) v = sigmoidf_(v) * e1[(size_t)m * lde1 + n]
                                                     * siluf_(e2[(size_t)m * lde2 + n]);
                else if (mode == 4) v += e1[(size_t)m * lde1 + n];
                size_t o = (size_t)m * ldc + n;
                if (Cf)  Cf[o] = v;
                if (Chi) split2(v, Chi + o, Clo + o);
            }
        }
    }
}

// ---------------- downsample by 2 ----------------
__global__ void down2(const float* __restrict__ src, int lds,
                      float* __restrict__ dst, int Tout)
{
    int idx = blockIdx.x * blockDim.x + threadIdx.x;
    int total = NB * Tout * DIN;
    if (idx >= total) return;
    int d = idx & (DIN - 1);
    int t = (idx >> 10) % Tout;
    int b = idx / (Tout * DIN);
    const float* p = src + (size_t)(b * 2 * Tout + 2 * t) * lds + d;
    dst[idx] = 0.5f * (p[0] + p[lds]);
}

// ---------------- depthwise causal conv (K=4) + bias + SiLU, batched ----------------
__global__ void conv_batched(const float* __restrict__ cw,
                             const float* __restrict__ cb)
{
    int z = blockIdx.y;
    int Tl = TLEN >> z;
    int total = NB * Tl * DIN;
    int idx = blockIdx.x * blockDim.x + threadIdx.x;
    if (idx >= total) return;
    const float* xin = (z == 0) ? g_xz : ((z == 1) ? g_xs1 : g_xs2);
    int ldx = (z == 0) ? 2 * DIN : DIN;
    size_t roff = (z == 0) ? 0 : ((z == 1) ? (size_t)R0 * DIN : (size_t)(R0 + R1) * DIN);
    const float* w = cw + z * DIN * 4;
    const float* bias = cb + z * DIN;

    int d = idx & (DIN - 1);
    int t = (idx >> 10) % Tl;
    int b = idx / (Tl * DIN);
    const float* base = xin + (size_t)(b * Tl) * ldx + d;
    float acc = bias[d];
    #pragma unroll
    for (int k = 0; k < 4; k++) {
        int tt = t + k - 3;
        if (tt >= 0) acc = fmaf(w[d * 4 + k], base[(size_t)tt * ldx], acc);
    }
    float v = siluf_(acc);
    g_xc[roff + idx] = v;
    split2(v, g_xcH + roff + idx, g_xcL + roff + idx);
}

// ---------------- selective scan, batched ----------------
__global__ void scan_batched(const float* __restrict__ A_log,
                             const float* __restrict__ Dp)
{
    const int z = blockIdx.y;
    const int Tl = TLEN >> z;
    const size_t roff  = (z == 0) ? 0 : ((z == 1) ? (size_t)R0 : (size_t)(R0 + R1));
    const float* xc   = g_xc   + roff * DIN;
    const float* proj = g_proj + roff * NPROJ;
    const float* dt   = g_dt   + roff * DIN;
    float*       y    = g_y    + roff * DIN;
    const float* Al   = A_log + z * DIN * DSTATE;
    const float* Dz   = Dp + z * DIN;

    const int j    = threadIdx.x & 15;
    const int dloc = threadIdx.x >> 4;
    const int b    = blockIdx.x >> 6;
    const int d0   = (blockIdx.x & 63) * 16;
    const int d    = d0 + dloc;

    __shared__ float s_dt[64][16];
    __shared__ float s_xc[64][16];
    __shared__ float s_B [64][17];
    __shared__ float s_C [64][17];

    const float Aj = -expf(Al[d * 16 + j]);
    const float Dv = Dz[d];
    float h = 0.0f;

    for (int t0 = 0; t0 < Tl; t0 += 64) {
        for (int i = threadIdx.x; i < 64 * 16; i += 256) {
            int tt = i >> 4, dl = i & 15;
            size_t rbase = (size_t)(b * Tl + t0 + tt);
            s_dt[tt][dl] = softplusf_(dt[rbase * DIN + d0 + dl]);
            s_xc[tt][dl] = xc[rbase * DIN + d0 + dl];
            const float* pr = proj + rbase * NPROJ;
            s_B[tt][dl] = pr[DTRANK + dl];
            s_C[tt][dl] = pr[DTRANK + DSTATE + dl];
        }
        __syncthreads();
        #pragma unroll 4
        for (int tt = 0; tt < 64; tt++) {
            float dtv = s_dt[tt][dloc];
            float xcv = s_xc[tt][dloc];
            float dA  = fmaxf(fexp(dtv * Aj), 1e-38f);
            float dBx = fmaxf(dtv * s_B[tt][j] * xcv, 1e-38f);
            h = fmaf(dA, h, dBx);
            float part = s_C[tt][j] * h;
            part += __shfl_xor_sync(0xffffffffu, part, 8);
            part += __shfl_xor_sync(0xffffffffu, part, 4);
            part += __shfl_xor_sync(0xffffffffu, part, 2);
            part += __shfl_xor_sync(0xffffffffu, part, 1);
            if (j == 0)
                y[(size_t)(b * Tl + t0 + tt) * DIN + d] = fmaf(Dv, xcv, part);
        }
        __syncthreads();
    }
}

// ---------------- softmax of scale weights ----------------
__global__ void compute_w(const float* __restrict__ sw)
{
    float a = sw[0], b = sw[1], c = sw[2];
    float m = fmaxf(a, fmaxf(b, c));
    float ea = expf(a - m), eb = expf(b - m), ec = expf(c - m);
    float s = ea + eb + ec;
    g_w[0] = ea / s; g_w[1] = eb / s; g_w[2] = ec / s;
}

// ---------------- fuse ----------------
__global__ void fuse_kernel()
{
    int idx = blockIdx.x * blockDim.x + threadIdx.x;
    int d = idx & (DIN - 1);
    int t = (idx >> 10) & (TLEN - 1);
    int b = idx >> 20;
    float o0 = g_y[idx];
    float o1 = g_y[(size_t)R0 * DIN + (size_t)(b * (TLEN/2) + (t >> 1)) * DIN + d];
    float o2 = g_y[(size_t)(R0 + R1) * DIN + (size_t)(b * (TLEN/4) + (t >> 2)) * DIN + d];
    g_fused[idx] = g_w[0] * o0 + g_w[1] * o1 + g_w[2] * o2;
    float c = (o0 + o1 + o2) * (1.0f / 3.0f);
    split2(c, g_cth + idx, g_ctl + idx);
}

// ---------------- LayerNorm ----------------
__global__ void ln_kernel(const float* __restrict__ gamma,
                          const float* __restrict__ beta,
                          float* __restrict__ out)
{
    int row = blockIdx.x;
    int tid = threadIdx.x;
    const float* r = g_pre + (size_t)row * DMODEL;
    float v1 = r[tid], v2 = r[tid + 256];
    float s  = v1 + v2;
    float q  = v1 * v1 + v2 * v2;
    #pragma unroll
    for (int o = 16; o > 0; o >>= 1) {
        s += __shfl_xor_sync(0xffffffffu, s, o);
        q += __shfl_xor_sync(0xffffffffu, q, o);
    }
    __shared__ float sh[8], sh2[8];
    int wid = tid >> 5, lane = tid & 31;
    if (lane == 0) { sh[wid] = s; sh2[wid] = q; }
    __syncthreads();
    if (tid == 0) {
        float ts = 0.f, tq = 0.f;
        #pragma unroll
        for (int i = 0; i < 8; i++) { ts += sh[i]; tq += sh2[i]; }
        sh[0] = ts; sh2[0] = tq;
    }
    __syncthreads();
    float mu  = sh[0] * (1.0f / DMODEL);
    float var = sh2[0] * (1.0f / DMODEL) - mu * mu;
    float inv = rsqrtf(var + 1e-5f);
    float* o = out + (size_t)row * DMODEL;
    o[tid]       = (v1 - mu) * inv * gamma[tid]       + beta[tid];
    o[tid + 256] = (v2 - mu) * inv * gamma[tid + 256] + beta[tid + 256];
}

// ---------------- driver ----------------
extern "C" void kernel_launch(void* const* d_in, const int* in_sizes, int n_in,
                              void* d_out, int out_size)
{
    const float* x        = (const float*)d_in[0];
    const float* in_proj  = (const float*)d_in[1];
    const float* conv_w   = (const float*)d_in[2];
    const float* conv_b   = (const float*)d_in[3];
    const float* xproj_w  = (const float*)d_in[4];
    const float* dtproj_w = (const float*)d_in[5];
    const float* dtproj_b = (const float*)d_in[6];
    const float* A_log    = (const float*)d_in[7];
    const float* D_p      = (const float*)d_in[8];
    const float* sw       = (const float*)d_in[9];
    const float* cg_w1    = (const float*)d_in[10];
    const float* cg_w2    = (const float*)d_in[11];
    const float* out_w    = (const float*)d_in[12];
    const float* ln_g     = (const float*)d_in[13];
    const float* ln_b     = (const float*)d_in[14];
    float* out            = (float*)d_out;

    static bool attr_set = false;
    if (!attr_set) {
        cudaFuncSetAttribute(gemm_bf16, cudaFuncAttributeMaxDynamicSharedMemorySize,
                             SMEM_BYTES);
        attr_set = true;
    }

    float *xz, *xs1, *xs2, *proj, *dtb, *fused, *pre;
    __nv_bfloat16 *xh,*xl,*wih,*wil,*xph,*xpl,*dwh,*dwl,*c1h,*c1l,*c2h,*c2l,*owh,*owl;
    __nv_bfloat16 *xcH,*xcL,*pH,*pL,*cth,*ctl,*h1h,*h1l,*ach,*acl;
    cudaGetSymbolAddress((void**)&xz,   g_xz);
    cudaGetSymbolAddress((void**)&xs1,  g_xs1);
    cudaGetSymbolAddress((void**)&xs2,  g_xs2);
    cudaGetSymbolAddress((void**)&proj, g_proj);
    cudaGetSymbolAddress((void**)&dtb,  g_dt);
    cudaGetSymbolAddress((void**)&fused,g_fused);
    cudaGetSymbolAddress((void**)&pre,  g_pre);
    cudaGetSymbolAddress((void**)&xh,  g_xh);   cudaGetSymbolAddress((void**)&xl,  g_xl);
    cudaGetSymbolAddress((void**)&wih, g_wih);  cudaGetSymbolAddress((void**)&wil, g_wil);
    cudaGetSymbolAddress((void**)&xph, g_xph);  cudaGetSymbolAddress((void**)&xpl, g_xpl);
    cudaGetSymbolAddress((void**)&dwh, g_dwh);  cudaGetSymbolAddress((void**)&dwl, g_dwl);
    cudaGetSymbolAddress((void**)&c1h, g_c1h);  cudaGetSymbolAddress((void**)&c1l, g_c1l);
    cudaGetSymbolAddress((void**)&c2h, g_c2h);  cudaGetSymbolAddress((void**)&c2l, g_c2l);
    cudaGetSymbolAddress((void**)&owh, g_owh);  cudaGetSymbolAddress((void**)&owl, g_owl);
    cudaGetSymbolAddress((void**)&xcH, g_xcH);  cudaGetSymbolAddress((void**)&xcL, g_xcL);
    cudaGetSymbolAddress((void**)&pH,  g_pH);   cudaGetSymbolAddress((void**)&pL,  g_pL);
    cudaGetSymbolAddress((void**)&cth, g_cth);  cudaGetSymbolAddress((void**)&ctl, g_ctl);
    cudaGetSymbolAddress((void**)&h1h, g_h1h);  cudaGetSymbolAddress((void**)&h1l, g_h1l);
    cudaGetSymbolAddress((void**)&ach, g_ach);  cudaGetSymbolAddress((void**)&acl, g_acl);

    const int4 M1   = make_int4(R0, 0, 0, 0);
    const int4 OFF0 = make_int4(0, 0, 0, 0);
    const int4 M3   = make_int4(R0, R1, R2, 0);
    const int4 OFF3 = make_int4(0, R0, R0 + R1, 0);

    // 0. split inputs + weights into bf16 planes
    split_all<<<(CU6/4 + 255)/256, 256>>>(x, in_proj, xproj_w, dtproj_w,
                                          cg_w1, cg_w2, out_w);

    // 1. in_proj
    gemm_bf16<<<dim3(32, 16, 1), 256, SMEM_BYTES>>>(
        xh, xl, DMODEL, wih, wil, DMODEL, 0,
        xz, nullptr, nullptr, 2*DIN, M1, OFF0, 2*DIN, DMODEL,
        nullptr, 0, 0, nullptr, 0, nullptr, 0);

    // 2. downsample
    down2<<<(R1*DIN)/256, 256>>>(xz, 2*DIN, xs1, TLEN/2);
    down2<<<(R2*DIN)/256, 256>>>(xs1, DIN,  xs2, TLEN/4);

    // 3. conv (batched)
    conv_batched<<<dim3((R0*DIN)/256, 3), 256>>>(conv_w, conv_b);

    // 4. xproj (batched)
    gemm_bf16<<<dim3(2, 16, 3), 256, SMEM_BYTES>>>(
        xcH, xcL, DIN, xph, xpl, DIN, NPROJ*DIN,
        proj, pH, pL, NPROJ, M3, OFF3, NPROJ, DIN,
        nullptr, 0, 0, nullptr, 0, nullptr, 0);

    // 5. dtproj (batched)
    gemm_bf16<<<dim3(16, 16, 3), 256, SMEM_BYTES>>>(
        pH, pL, NPROJ, dwh, dwl, DTRANK, DIN*DTRANK,
        dtb, nullptr, nullptr, DIN, M3, OFF3, DIN, DTRANK,
        dtproj_b, DIN, 1, nullptr, 0, nullptr, 0);

    // 6. selective scan (batched)
    scan_batched<<<dim3(128, 3), 256>>>(A_log, D_p);

    // 7. fuse
    compute_w<<<1, 1>>>(sw);
    fuse_kernel<<<(R0*DIN)/256, 256>>>();

    // 8. context gate
    gemm_bf16<<<dim3(8, 16, 1), 256, SMEM_BYTES>>>(
        cth, ctl, DIN, c1h, c1l, DIN, 0,
        nullptr, h1h, h1l, DIN/2, M1, OFF0, DIN/2, DIN,
        nullptr, 0, 2, nullptr, 0, nullptr, 0);
    gemm_bf16<<<dim3(16, 16, 1), 256, SMEM_BYTES>>>(
        h1h, h1l, DIN/2, c2h, c2l, DIN/2, 0,
        nullptr, ach, acl, DIN, M1, OFF0, DIN, DIN/2,
        nullptr, 0, 3, fused, DIN, xz + DIN, 2*DIN);

    // 9. out_proj + residual
    gemm_bf16<<<dim3(8, 16, 1), 256, SMEM_BYTES>>>(
        ach, acl, DIN, owh, owl, DIN, 0,
        pre, nullptr, nullptr, DMODEL, M1, OFF0, DMODEL, DIN,
        nullptr, 0, 4, x, DMODEL, nullptr, 0);

    // 10. LayerNorm
    ln_kernel<<<R0, 256>>>(ln_g, ln_b, out);
}

// round 7
// speedup vs baseline: 2.0887x; 1.1092x over previous
#include <cuda_runtime.h>
#include <cuda_fp16.h>
#include <stdint.h>
#include <math.h>

// ---------------- problem constants ----------------
#define NB      2
#define TLEN    1024
#define DMODEL  512
#define DIN     1024
#define DTRANK  64
#define DSTATE  16
#define NPROJ   96

#define R0 2048
#define R1 1024
#define R2 512
#define RSUM (R0+R1+R2)

// ---------------- fp32 scratch ----------------
__device__ float g_xz   [R0*2*DIN];
__device__ float g_xs1  [R1*DIN];
__device__ float g_xs2  [R2*DIN];
__device__ float g_xc   [RSUM*DIN];
__device__ float g_proj [RSUM*NPROJ];
__device__ float g_dt   [RSUM*DIN];
__device__ float g_y    [RSUM*DIN];
__device__ float g_fused[R0*DIN];
__device__ float g_pre  [R0*DMODEL];
__device__ float g_w    [4];

// ---------------- fp16 planes: A-operands get hi+lo, W-operands hi only ----------------
__device__ __half g_xh [R0*DMODEL],     g_xl [R0*DMODEL];
__device__ __half g_wih[2*DIN*DMODEL];
__device__ __half g_xph[3*NPROJ*DIN];
__device__ __half g_dwh[3*DIN*DTRANK];
__device__ __half g_c1h[(DIN/2)*DIN];
__device__ __half g_c2h[DIN*(DIN/2)];
__device__ __half g_owh[DMODEL*DIN];
__device__ __half g_xcH[RSUM*DIN],      g_xcL[RSUM*DIN];
__device__ __half g_pH [RSUM*NPROJ],    g_pL [RSUM*NPROJ];
__device__ __half g_cth[R0*DIN],        g_ctl[R0*DIN];
__device__ __half g_h1h[R0*(DIN/2)],    g_h1l[R0*(DIN/2)];
__device__ __half g_ach[R0*DIN],        g_acl[R0*DIN];

// ---------------- math helpers ----------------
__device__ __forceinline__ float fexp(float x) {
    float t = x * 1.4426950408889634f;
    t = fminf(fmaxf(t, -126.0f), 126.0f);
    float fi = rintf(t);
    float f  = t - fi;
    float p  = 1.5403530393e-4f;
    p = fmaf(p, f, 1.3333558146e-3f);
    p = fmaf(p, f, 9.6181291076e-3f);
    p = fmaf(p, f, 5.5504108664e-2f);
    p = fmaf(p, f, 2.4022650695e-1f);
    p = fmaf(p, f, 6.9314718056e-1f);
    p = fmaf(p, f, 1.0f);
    float sc = __int_as_float(((int)fi + 127) << 23);
    return sc * p;
}
__device__ __forceinline__ float sigmoidf_(float x) {
    return __fdividef(1.0f, 1.0f + fexp(-x));
}
__device__ __forceinline__ float siluf_(float x) { return x * sigmoidf_(x); }
__device__ __forceinline__ float softplusf_(float x) {
    return fmaxf(x, 0.0f) + log1pf(fexp(-fabsf(x)));
}
__device__ __forceinline__ void split2h(float v, __half* h, __half* l) {
    __half hi = __float2half(v);
    *h = hi;
    *l = __float2half(v - __half2float(hi));
}

// ---------------- split inputs/weights into fp16 planes ----------------
// x: hi+lo. Weights: hi only.
#define SEG0 (R0*DMODEL)
#define SEG1 (2*DIN*DMODEL)
#define SEG2 (3*NPROJ*DIN)
#define SEG3 (3*DIN*DTRANK)
#define SEG4 ((DIN/2)*DIN)
#define SEG5 (DIN*(DIN/2))
#define SEG6 (DMODEL*DIN)
#define CU0 (SEG0)
#define CU1 (CU0+SEG1)
#define CU2 (CU1+SEG2)
#define CU3 (CU2+SEG3)
#define CU4 (CU3+SEG4)
#define CU5 (CU4+SEG5)
#define CU6 (CU5+SEG6)

__global__ void split_all(const float* __restrict__ x,
                          const float* __restrict__ w1,
                          const float* __restrict__ w2,
                          const float* __restrict__ w3,
                          const float* __restrict__ w4,
                          const float* __restrict__ w5,
                          const float* __restrict__ w6)
{
    long i = ((long)blockIdx.x * blockDim.x + threadIdx.x) * 4;
    if (i >= CU6) return;
    const float* src; __half* dh; __half* dl; long off;
    if      (i < CU0) { src=x;  dh=g_xh;  dl=g_xl;   off=0;   }
    else if (i < CU1) { src=w1; dh=g_wih; dl=nullptr; off=CU0; }
    else if (i < CU2) { src=w2; dh=g_xph; dl=nullptr; off=CU1; }
    else if (i < CU3) { src=w3; dh=g_dwh; dl=nullptr; off=CU2; }
    else if (i < CU4) { src=w4; dh=g_c1h; dl=nullptr; off=CU3; }
    else if (i < CU5) { src=w5; dh=g_c2h; dl=nullptr; off=CU4; }
    else              { src=w6; dh=g_owh; dl=nullptr; off=CU5; }
    long j = i - off;
    float4 v = *(const float4*)(src + j);
    float va[4];
    va[0]=v.x; va[1]=v.y; va[2]=v.z; va[3]=v.w;
    if (dl) {
        #pragma unroll
        for (int q = 0; q < 4; q++) split2h(va[q], dh+j+q, dl+j+q);
    } else {
        #pragma unroll
        for (int q = 0; q < 4; q++) dh[j+q] = __float2half(va[q]);
    }
}

// ---------------- 3-stage pipelined tensor-core GEMM (fp16 2-term split) ----------------
// C[m,n] = epi( sum_k A[m,k]*W[n,k] ), A = Ah+Al (fp16 planes), W = Wh (fp16).
// 2 MMAs per tile: Ah*Wh + Al*Wh.  BM=128, BN=64, BK=32, 256 thr = 8 warps.
#define ASTR 40
#define APL (128*ASTR)
#define BPL (64*ASTR)
#define STG (2*APL + BPL)              // 12800 elems per stage
#define NSTAGE 3
#define SMEM_BYTES (NSTAGE*STG*2)      // 76800 B

__device__ __forceinline__ void ldm_x4(unsigned int* r, const __half* p) {
    unsigned int a = (unsigned int)__cvta_generic_to_shared(p);
    asm volatile("ldmatrix.sync.aligned.m8n8.x4.shared.b16 {%0,%1,%2,%3}, [%4];"
                 : "=r"(r[0]), "=r"(r[1]), "=r"(r[2]), "=r"(r[3]) : "r"(a));
}
__device__ __forceinline__ void mma16816(float* c, const unsigned int* a,
                                         const unsigned int* b) {
    asm volatile(
        "mma.sync.aligned.m16n8k16.row.col.f32.f16.f16.f32 "
        "{%0,%1,%2,%3}, {%4,%5,%6,%7}, {%8,%9}, {%0,%1,%2,%3};"
        : "+f"(c[0]), "+f"(c[1]), "+f"(c[2]), "+f"(c[3])
        : "r"(a[0]), "r"(a[1]), "r"(a[2]), "r"(a[3]), "r"(b[0]), "r"(b[1]));
}
__device__ __forceinline__ void cp16(unsigned int dst, const void* src, bool pred) {
    int sz = pred ? 16 : 0;
    asm volatile("cp.async.cg.shared.global [%0], [%1], 16, %2;\n"
                 :: "r"(dst), "l"(src), "r"(sz));
}

__global__ void __launch_bounds__(256, 2) gemm_f16(
    const __half* __restrict__ Ahi, const __half* __restrict__ Alo, int lda,
    const __half* __restrict__ Whi, int ldb, int wstride,
    float* Cf, __half* Chi, __half* Clo, int ldc,
    int4 Ms, int4 rowoffs, int N, int K,
    const float* bias, int bstride, int mode,
    const float* e1, int lde1, const float* e2, int lde2)
{
    extern __shared__ __align__(16) __half sm[];
    const int z = blockIdx.z;
    const int M      = (z == 0) ? Ms.x      : ((z == 1) ? Ms.y      : Ms.z);
    const int rowoff = (z == 0) ? rowoffs.x : ((z == 1) ? rowoffs.y : rowoffs.z);
    const int m0 = blockIdx.y * 128;
    if (m0 >= M) return;
    const int n0 = blockIdx.x * 64;

    const int tid = threadIdx.x, lane = tid & 31, wid = tid >> 5;
    const int wm = wid & 3, wn = wid >> 2;

    const __half* Ah = Ahi + (size_t)rowoff * lda;
    const __half* Al = Alo + (size_t)rowoff * lda;
    const __half* Wh = Whi + (size_t)z * wstride;

    const int arow = tid >> 1, acol = (tid & 1) * 16;
    const int brow = tid >> 2, bcol = (tid & 3) * 8;
    const bool bv = (n0 + brow) < N;

    const __half* agh = Ah + (size_t)(m0 + arow) * lda + acol;
    const __half* agl = Al + (size_t)(m0 + arow) * lda + acol;
    const __half* bgh = Wh + (size_t)(n0 + brow) * ldb + bcol;

    unsigned int sbase = (unsigned int)__cvta_generic_to_shared(sm);
    const int a_dst = arow * ASTR + acol;
    const int b_dst = brow * ASTR + bcol;

    float acc[2][4][4];
    #pragma unroll
    for (int i = 0; i < 2; i++)
        #pragma unroll
        for (int j = 0; j < 4; j++)
            #pragma unroll
            for (int r = 0; r < 4; r++) acc[i][j][r] = 0.0f;

    const int aoff = (wm * 32 + (lane & 15)) * ASTR + (lane >> 4) * 8;
    const int boff = (wn * 32 + ((lane >> 4) << 3) + (lane & 7)) * ASTR
                   + ((lane >> 3) & 1) * 8;

    const int nk = K / 32;

    auto issue = [&](int s) {
        int k0 = s * 32;
        unsigned int st = sbase + (unsigned int)(s % NSTAGE) * (STG * 2);
        cp16(st + (a_dst) * 2,           agh + k0,     true);
        cp16(st + (a_dst + 8) * 2,       agh + k0 + 8, true);
        cp16(st + (APL + a_dst) * 2,     agl + k0,     true);
        cp16(st + (APL + a_dst + 8) * 2, agl + k0 + 8, true);
        cp16(st + (2 * APL + b_dst) * 2, bgh + k0,     bv);
    };

    #pragma unroll
    for (int s = 0; s < NSTAGE - 1; s++) {
        if (s < nk) issue(s);
        asm volatile("cp.async.commit_group;\n");
    }

    for (int it = 0; it < nk; it++) {
        asm volatile("cp.async.wait_group %0;\n" :: "n"(NSTAGE - 2));
        __syncthreads();

        int pf = it + NSTAGE - 1;
        if (pf < nk) issue(pf);
        asm volatile("cp.async.commit_group;\n");

        const __half* st = sm + (it % NSTAGE) * STG;
        #pragma unroll
        for (int k16 = 0; k16 < 2; k16++) {
            unsigned int ahif[8];
            unsigned int alof[8];
            unsigned int bhif[8];
            const __half* pa = st + aoff + k16 * 16;
            ldm_x4(&ahif[0], pa);
            ldm_x4(&ahif[4], pa + 16 * ASTR);
            ldm_x4(&alof[0], pa + APL);
            ldm_x4(&alof[4], pa + APL + 16 * ASTR);
            const __half* pb = st + 2 * APL + boff + k16 * 16;
            ldm_x4(&bhif[0], pb);
            ldm_x4(&bhif[4], pb + 16 * ASTR);
            #pragma unroll
            for (int mi = 0; mi < 2; mi++) {
                #pragma unroll
                for (int ni = 0; ni < 4; ni++) {
                    mma16816(acc[mi][ni], &ahif[mi * 4], &bhif[ni * 2]);
                    mma16816(acc[mi][ni], &alof[mi * 4], &bhif[ni * 2]);
                }
            }
        }
    }

    // ---- epilogue ----
    #pragma unroll
    for (int mi = 0; mi < 2; mi++) {
        #pragma unroll
        for (int ni = 0; ni < 4; ni++) {
            int mb = m0 + wm * 32 + mi * 16 + (lane >> 2);
            int nb = n0 + wn * 32 + ni * 8 + (lane & 3) * 2;
            #pragma unroll
            for (int r = 0; r < 4; r++) {
                int mloc = mb + ((r >> 1) << 3);
                int n = nb + (r & 1);
                if (n >= N) continue;
                int m = rowoff + mloc;
                float v = acc[mi][ni][r];
                if (mode == 1)      v += bias[z * bstride + n];
                else if (mode == 2) v = siluf_(v);
                else if (mode == 3) v = sigmoidf_(v) * e1[(size_t)m * lde1 + n]
                                                     * siluf_(e2[(size_t)m * lde2 + n]);
                else if (mode == 4) v += e1[(size_t)m * lde1 + n];
                size_t o = (size_t)m * ldc + n;
                if (Cf)  Cf[o] = v;
                if (Chi) split2h(v, Chi + o, Clo + o);
            }
        }
    }
}

// ---------------- downsample by 2 ----------------
__global__ void down2(const float* __restrict__ src, int lds,
                      float* __restrict__ dst, int Tout)
{
    int idx = blockIdx.x * blockDim.x + threadIdx.x;
    int total = NB * Tout * DIN;
    if (idx >= total) return;
    int d = idx & (DIN - 1);
    int t = (idx >> 10) % Tout;
    int b = idx / (Tout * DIN);
    const float* p = src + (size_t)(b * 2 * Tout + 2 * t) * lds + d;
    dst[idx] = 0.5f * (p[0] + p[lds]);
}

// ---------------- depthwise causal conv (K=4) + bias + SiLU, batched ----------------
__global__ void conv_batched(const float* __restrict__ cw,
                             const float* __restrict__ cb)
{
    int z = blockIdx.y;
    int Tl = TLEN >> z;
    int total = NB * Tl * DIN;
    int idx = blockIdx.x * blockDim.x + threadIdx.x;
    if (idx >= total) return;
    const float* xin = (z == 0) ? g_xz : ((z == 1) ? g_xs1 : g_xs2);
    int ldx = (z == 0) ? 2 * DIN : DIN;
    size_t roff = (z == 0) ? 0 : ((z == 1) ? (size_t)R0 * DIN : (size_t)(R0 + R1) * DIN);
    const float* w = cw + z * DIN * 4;
    const float* bias = cb + z * DIN;

    int d = idx & (DIN - 1);
    int t = (idx >> 10) % Tl;
    int b = idx / (Tl * DIN);
    const float* base = xin + (size_t)(b * Tl) * ldx + d;
    float acc = bias[d];
    #pragma unroll
    for (int k = 0; k < 4; k++) {
        int tt = t + k - 3;
        if (tt >= 0) acc = fmaf(w[d * 4 + k], base[(size_t)tt * ldx], acc);
    }
    float v = siluf_(acc);
    g_xc[roff + idx] = v;
    split2h(v, g_xcH + roff + idx, g_xcL + roff + idx);
}

// ---------------- selective scan, batched ----------------
__global__ void scan_batched(const float* __restrict__ A_log,
                             const float* __restrict__ Dp)
{
    const int z = blockIdx.y;
    const int Tl = TLEN >> z;
    const size_t roff  = (z == 0) ? 0 : ((z == 1) ? (size_t)R0 : (size_t)(R0 + R1));
    const float* xc   = g_xc   + roff * DIN;
    const float* proj = g_proj + roff * NPROJ;
    const float* dt   = g_dt   + roff * DIN;
    float*       y    = g_y    + roff * DIN;
    const float* Al   = A_log + z * DIN * DSTATE;
    const float* Dz   = Dp + z * DIN;

    const int j    = threadIdx.x & 15;
    const int dloc = threadIdx.x >> 4;
    const int b    = blockIdx.x >> 6;
    const int d0   = (blockIdx.x & 63) * 16;
    const int d    = d0 + dloc;

    __shared__ float s_dt[64][16];
    __shared__ float s_xc[64][16];
    __shared__ float s_B [64][17];
    __shared__ float s_C [64][17];

    const float Aj = -expf(Al[d * 16 + j]);
    const float Dv = Dz[d];
    float h = 0.0f;

    for (int t0 = 0; t0 < Tl; t0 += 64) {
        for (int i = threadIdx.x; i < 64 * 16; i += 256) {
            int tt = i >> 4, dl = i & 15;
            size_t rbase = (size_t)(b * Tl + t0 + tt);
            s_dt[tt][dl] = softplusf_(dt[rbase * DIN + d0 + dl]);
            s_xc[tt][dl] = xc[rbase * DIN + d0 + dl];
            const float* pr = proj + rbase * NPROJ;
            s_B[tt][dl] = pr[DTRANK + dl];
            s_C[tt][dl] = pr[DTRANK + DSTATE + dl];
        }
        __syncthreads();
        #pragma unroll 4
        for (int tt = 0; tt < 64; tt++) {
            float dtv = s_dt[tt][dloc];
            float xcv = s_xc[tt][dloc];
            float dA  = fmaxf(fexp(dtv * Aj), 1e-38f);
            float dBx = fmaxf(dtv * s_B[tt][j] * xcv, 1e-38f);
            h = fmaf(dA, h, dBx);
            float part = s_C[tt][j] * h;
            part += __shfl_xor_sync(0xffffffffu, part, 8);
            part += __shfl_xor_sync(0xffffffffu, part, 4);
            part += __shfl_xor_sync(0xffffffffu, part, 2);
            part += __shfl_xor_sync(0xffffffffu, part, 1);
            if (j == 0)
                y[(size_t)(b * Tl + t0 + tt) * DIN + d] = fmaf(Dv, xcv, part);
        }
        __syncthreads();
    }
}

// ---------------- softmax of scale weights ----------------
__global__ void compute_w(const float* __restrict__ sw)
{
    float a = sw[0], b = sw[1], c = sw[2];
    float m = fmaxf(a, fmaxf(b, c));
    float ea = expf(a - m), eb = expf(b - m), ec = expf(c - m);
    float s = ea + eb + ec;
    g_w[0] = ea / s; g_w[1] = eb / s; g_w[2] = ec / s;
}

// ---------------- fuse ----------------
__global__ void fuse_kernel()
{
    int idx = blockIdx.x * blockDim.x + threadIdx.x;
    int d = idx & (DIN - 1);
    int t = (idx >> 10) & (TLEN - 1);
    int b = idx >> 20;
    float o0 = g_y[idx];
    float o1 = g_y[(size_t)R0 * DIN + (size_t)(b * (TLEN/2) + (t >> 1)) * DIN + d];
    float o2 = g_y[(size_t)(R0 + R1) * DIN + (size_t)(b * (TLEN/4) + (t >> 2)) * DIN + d];
    g_fused[idx] = g_w[0] * o0 + g_w[1] * o1 + g_w[2] * o2;
    float c = (o0 + o1 + o2) * (1.0f / 3.0f);
    split2h(c, g_cth + idx, g_ctl + idx);
}

// ---------------- LayerNorm ----------------
__global__ void ln_kernel(const float* __restrict__ gamma,
                          const float* __restrict__ beta,
                          float* __restrict__ out)
{
    int row = blockIdx.x;
    int tid = threadIdx.x;
    const float* r = g_pre + (size_t)row * DMODEL;
    float v1 = r[tid], v2 = r[tid + 256];
    float s  = v1 + v2;
    float q  = v1 * v1 + v2 * v2;
    #pragma unroll
    for (int o = 16; o > 0; o >>= 1) {
        s += __shfl_xor_sync(0xffffffffu, s, o);
        q += __shfl_xor_sync(0xffffffffu, q, o);
    }
    __shared__ float sh[8], sh2[8];
    int wid = tid >> 5, lane = tid & 31;
    if (lane == 0) { sh[wid] = s; sh2[wid] = q; }
    __syncthreads();
    if (tid == 0) {
        float ts = 0.f, tq = 0.f;
        #pragma unroll
        for (int i = 0; i < 8; i++) { ts += sh[i]; tq += sh2[i]; }
        sh[0] = ts; sh2[0] = tq;
    }
    __syncthreads();
    float mu  = sh[0] * (1.0f / DMODEL);
    float var = sh2[0] * (1.0f / DMODEL) - mu * mu;
    float inv = rsqrtf(var + 1e-5f);
    float* o = out + (size_t)row * DMODEL;
    o[tid]       = (v1 - mu) * inv * gamma[tid]       + beta[tid];
    o[tid + 256] = (v2 - mu) * inv * gamma[tid + 256] + beta[tid + 256];
}

// ---------------- driver ----------------
extern "C" void kernel_launch(void* const* d_in, const int* in_sizes, int n_in,
                              void* d_out, int out_size)
{
    const float* x        = (const float*)d_in[0];
    const float* in_proj  = (const float*)d_in[1];
    const float* conv_w   = (const float*)d_in[2];
    const float* conv_b   = (const float*)d_in[3];
    const float* xproj_w  = (const float*)d_in[4];
    const float* dtproj_w = (const float*)d_in[5];
    const float* dtproj_b = (const float*)d_in[6];
    const float* A_log    = (const float*)d_in[7];
    const float* D_p      = (const float*)d_in[8];
    const float* sw       = (const float*)d_in[9];
    const float* cg_w1    = (const float*)d_in[10];
    const float* cg_w2    = (const float*)d_in[11];
    const float* out_w    = (const float*)d_in[12];
    const float* ln_g     = (const float*)d_in[13];
    const float* ln_b     = (const float*)d_in[14];
    float* out            = (float*)d_out;

    static bool attr_set = false;
    if (!attr_set) {
        cudaFuncSetAttribute(gemm_f16, cudaFuncAttributeMaxDynamicSharedMemorySize,
                             SMEM_BYTES);
        attr_set = true;
    }

    float *xz, *xs1, *xs2, *proj, *dtb, *fused, *pre;
    __half *xh,*xl,*wih,*xph,*dwh,*c1h,*c2h,*owh;
    __half *xcH,*xcL,*pH,*pL,*cth,*ctl,*h1h,*h1l,*ach,*acl;
    cudaGetSymbolAddress((void**)&xz,   g_xz);
    cudaGetSymbolAddress((void**)&xs1,  g_xs1);
    cudaGetSymbolAddress((void**)&xs2,  g_xs2);
    cudaGetSymbolAddress((void**)&proj, g_proj);
    cudaGetSymbolAddress((void**)&dtb,  g_dt);
    cudaGetSymbolAddress((void**)&fused,g_fused);
    cudaGetSymbolAddress((void**)&pre,  g_pre);
    cudaGetSymbolAddress((void**)&xh,  g_xh);   cudaGetSymbolAddress((void**)&xl,  g_xl);
    cudaGetSymbolAddress((void**)&wih, g_wih);
    cudaGetSymbolAddress((void**)&xph, g_xph);
    cudaGetSymbolAddress((void**)&dwh, g_dwh);
    cudaGetSymbolAddress((void**)&c1h, g_c1h);
    cudaGetSymbolAddress((void**)&c2h, g_c2h);
    cudaGetSymbolAddress((void**)&owh, g_owh);
    cudaGetSymbolAddress((void**)&xcH, g_xcH);  cudaGetSymbolAddress((void**)&xcL, g_xcL);
    cudaGetSymbolAddress((void**)&pH,  g_pH);   cudaGetSymbolAddress((void**)&pL,  g_pL);
    cudaGetSymbolAddress((void**)&cth, g_cth);  cudaGetSymbolAddress((void**)&ctl, g_ctl);
    cudaGetSymbolAddress((void**)&h1h, g_h1h);  cudaGetSymbolAddress((void**)&h1l, g_h1l);
    cudaGetSymbolAddress((void**)&ach, g_ach);  cudaGetSymbolAddress((void**)&acl, g_acl);

    const int4 M1   = make_int4(R0, 0, 0, 0);
    const int4 OFF0 = make_int4(0, 0, 0, 0);
    const int4 M3   = make_int4(R0, R1, R2, 0);
    const int4 OFF3 = make_int4(0, R0, R0 + R1, 0);

    // 0. split inputs + weights into fp16 planes
    split_all<<<(CU6/4 + 255)/256, 256>>>(x, in_proj, xproj_w, dtproj_w,
                                          cg_w1, cg_w2, out_w);

    // 1. in_proj
    gemm_f16<<<dim3(32, 16, 1), 256, SMEM_BYTES>>>(
        xh, xl, DMODEL, wih, DMODEL, 0,
        xz, nullptr, nullptr, 2*DIN, M1, OFF0, 2*DIN, DMODEL,
        nullptr, 0, 0, nullptr, 0, nullptr, 0);

    // 2. downsample
    down2<<<(R1*DIN)/256, 256>>>(xz, 2*DIN, xs1, TLEN/2);
    down2<<<(R2*DIN)/256, 256>>>(xs1, DIN,  xs2, TLEN/4);

    // 3. conv (batched)
    conv_batched<<<dim3((R0*DIN)/256, 3), 256>>>(conv_w, conv_b);

    // 4. xproj (batched): N=96, K=1024
    gemm_f16<<<dim3(2, 16, 3), 256, SMEM_BYTES>>>(
        xcH, xcL, DIN, xph, DIN, NPROJ*DIN,
        proj, pH, pL, NPROJ, M3, OFF3, NPROJ, DIN,
        nullptr, 0, 0, nullptr, 0, nullptr, 0);

    // 5. dtproj (batched): N=1024, K=64 (+bias)
    gemm_f16<<<dim3(16, 16, 3), 256, SMEM_BYTES>>>(
        pH, pL, NPROJ, dwh, DTRANK, DIN*DTRANK,
        dtb, nullptr, nullptr, DIN, M3, OFF3, DIN, DTRANK,
        dtproj_b, DIN, 1, nullptr, 0, nullptr, 0);

    // 6. selective scan (batched)
    scan_batched<<<dim3(128, 3), 256>>>(A_log, D_p);

    // 7. fuse
    compute_w<<<1, 1>>>(sw);
    fuse_kernel<<<(R0*DIN)/256, 256>>>();

    // 8. context gate
    gemm_f16<<<dim3(8, 16, 1), 256, SMEM_BYTES>>>(
        cth, ctl, DIN, c1h, DIN, 0,
        nullptr, h1h, h1l, DIN/2, M1, OFF0, DIN/2, DIN,
        nullptr, 0, 2, nullptr, 0, nullptr, 0);
    gemm_f16<<<dim3(16, 16, 1), 256, SMEM_BYTES>>>(
        h1h, h1l, DIN/2, c2h, DIN/2, 0,
        nullptr, ach, acl, DIN, M1, OFF0, DIN, DIN/2,
        nullptr, 0, 3, fused, DIN, xz + DIN, 2*DIN);

    // 9. out_proj + residual
    gemm_f16<<<dim3(8, 16, 1), 256, SMEM_BYTES>>>(
        ach, acl, DIN, owh, DIN, 0,
        pre, nullptr, nullptr, DMODEL, M1, OFF0, DMODEL, DIN,
        nullptr, 0, 4, x, DMODEL, nullptr, 0);

    // 10. LayerNorm
    ln_kernel<<<R0, 256>>>(ln_g, ln_b, out);
}

// round 8
// speedup vs baseline: 2.5278x; 1.2102x over previous
#include <cuda_runtime.h>
#include <cuda_fp16.h>
#include <stdint.h>
#include <math.h>

// ---------------- problem constants ----------------
#define NB      2
#define TLEN    1024
#define DMODEL  512
#define DIN     1024
#define DTRANK  64
#define DSTATE  16
#define NPROJ   96

#define R0 2048
#define R1 1024
#define R2 512
#define RSUM (R0+R1+R2)

// ---------------- fp32 scratch ----------------
__device__ float g_xz   [R0*2*DIN];
__device__ float g_xs1  [R1*DIN];
__device__ float g_xs2  [R2*DIN];
__device__ float g_xc   [RSUM*DIN];
__device__ float g_proj [RSUM*NPROJ];
__device__ float g_dt   [RSUM*DIN];
__device__ float g_y    [RSUM*DIN];
__device__ float g_fused[R0*DIN];
__device__ float g_pre  [R0*DMODEL];
__device__ float g_w    [4];

// ---------------- fp16 planes (single plane everywhere) ----------------
__device__ __half g_xh [R0*DMODEL];
__device__ __half g_wih[2*DIN*DMODEL];
__device__ __half g_xph[3*NPROJ*DIN];
__device__ __half g_dwh[3*DIN*DTRANK];
__device__ __half g_c1h[(DIN/2)*DIN];
__device__ __half g_c2h[DIN*(DIN/2)];
__device__ __half g_owh[DMODEL*DIN];
__device__ __half g_xcH[RSUM*DIN];
__device__ __half g_pH [RSUM*NPROJ];
__device__ __half g_cth[R0*DIN];
__device__ __half g_h1h[R0*(DIN/2)];
__device__ __half g_ach[R0*DIN];

// ---------------- math helpers ----------------
__device__ __forceinline__ float fexp(float x) {
    float t = x * 1.4426950408889634f;
    t = fminf(fmaxf(t, -126.0f), 126.0f);
    float fi = rintf(t);
    float f  = t - fi;
    float p  = 1.5403530393e-4f;
    p = fmaf(p, f, 1.3333558146e-3f);
    p = fmaf(p, f, 9.6181291076e-3f);
    p = fmaf(p, f, 5.5504108664e-2f);
    p = fmaf(p, f, 2.4022650695e-1f);
    p = fmaf(p, f, 6.9314718056e-1f);
    p = fmaf(p, f, 1.0f);
    float sc = __int_as_float(((int)fi + 127) << 23);
    return sc * p;
}
__device__ __forceinline__ float sigmoidf_(float x) {
    return __fdividef(1.0f, 1.0f + fexp(-x));
}
__device__ __forceinline__ float siluf_(float x) { return x * sigmoidf_(x); }
__device__ __forceinline__ float softplusf_(float x) {
    return fmaxf(x, 0.0f) + log1pf(fexp(-fabsf(x)));
}

// ---------------- convert inputs/weights into fp16 planes ----------------
#define SEG0 (R0*DMODEL)
#define SEG1 (2*DIN*DMODEL)
#define SEG2 (3*NPROJ*DIN)
#define SEG3 (3*DIN*DTRANK)
#define SEG4 ((DIN/2)*DIN)
#define SEG5 (DIN*(DIN/2))
#define SEG6 (DMODEL*DIN)
#define CU0 (SEG0)
#define CU1 (CU0+SEG1)
#define CU2 (CU1+SEG2)
#define CU3 (CU2+SEG3)
#define CU4 (CU3+SEG4)
#define CU5 (CU4+SEG5)
#define CU6 (CU5+SEG6)

__global__ void split_all(const float* __restrict__ x,
                          const float* __restrict__ w1,
                          const float* __restrict__ w2,
                          const float* __restrict__ w3,
                          const float* __restrict__ w4,
                          const float* __restrict__ w5,
                          const float* __restrict__ w6)
{
    long i = ((long)blockIdx.x * blockDim.x + threadIdx.x) * 4;
    if (i >= CU6) return;
    const float* src; __half* dh; long off;
    if      (i < CU0) { src=x;  dh=g_xh;  off=0;   }
    else if (i < CU1) { src=w1; dh=g_wih; off=CU0; }
    else if (i < CU2) { src=w2; dh=g_xph; off=CU1; }
    else if (i < CU3) { src=w3; dh=g_dwh; off=CU2; }
    else if (i < CU4) { src=w4; dh=g_c1h; off=CU3; }
    else if (i < CU5) { src=w5; dh=g_c2h; off=CU4; }
    else              { src=w6; dh=g_owh; off=CU5; }
    long j = i - off;
    float4 v = *(const float4*)(src + j);
    __half2 lo = __floats2half2_rn(v.x, v.y);
    __half2 hi = __floats2half2_rn(v.z, v.w);
    *(__half2*)(dh + j)     = lo;
    *(__half2*)(dh + j + 2) = hi;
}

// ---------------- 3-stage pipelined tensor-core GEMM (pure fp16) ----------------
// C[m,n] = epi( sum_k A[m,k]*W[n,k] ).  BM=128, BN=64, BK=32, 256 thr = 8 warps.
#define ASTR 40
#define APL (128*ASTR)
#define BPL (64*ASTR)
#define STG (APL + BPL)                // 7680 elems per stage
#define NSTAGE 3
#define SMEM_BYTES (NSTAGE*STG*2)      // 46080 B

__device__ __forceinline__ void ldm_x4(unsigned int* r, const __half* p) {
    unsigned int a = (unsigned int)__cvta_generic_to_shared(p);
    asm volatile("ldmatrix.sync.aligned.m8n8.x4.shared.b16 {%0,%1,%2,%3}, [%4];"
                 : "=r"(r[0]), "=r"(r[1]), "=r"(r[2]), "=r"(r[3]) : "r"(a));
}
__device__ __forceinline__ void mma16816(float* c, const unsigned int* a,
                                         const unsigned int* b) {
    asm volatile(
        "mma.sync.aligned.m16n8k16.row.col.f32.f16.f16.f32 "
        "{%0,%1,%2,%3}, {%4,%5,%6,%7}, {%8,%9}, {%0,%1,%2,%3};"
        : "+f"(c[0]), "+f"(c[1]), "+f"(c[2]), "+f"(c[3])
        : "r"(a[0]), "r"(a[1]), "r"(a[2]), "r"(a[3]), "r"(b[0]), "r"(b[1]));
}
__device__ __forceinline__ void cp16(unsigned int dst, const void* src, bool pred) {
    int sz = pred ? 16 : 0;
    asm volatile("cp.async.cg.shared.global [%0], [%1], 16, %2;\n"
                 :: "r"(dst), "l"(src), "r"(sz));
}

__global__ void __launch_bounds__(256, 2) gemm_f16(
    const __half* __restrict__ Ahi, int lda,
    const __half* __restrict__ Whi, int ldb, int wstride,
    float* Cf, __half* Chi, int ldc,
    int4 Ms, int4 rowoffs, int N, int K,
    const float* bias, int bstride, int mode,
    const float* e1, int lde1, const float* e2, int lde2)
{
    extern __shared__ __align__(16) __half sm[];
    const int z = blockIdx.z;
    const int M      = (z == 0) ? Ms.x      : ((z == 1) ? Ms.y      : Ms.z);
    const int rowoff = (z == 0) ? rowoffs.x : ((z == 1) ? rowoffs.y : rowoffs.z);
    const int m0 = blockIdx.y * 128;
    if (m0 >= M) return;
    const int n0 = blockIdx.x * 64;

    const int tid = threadIdx.x, lane = tid & 31, wid = tid >> 5;
    const int wm = wid & 3, wn = wid >> 2;

    const __half* Ah = Ahi + (size_t)rowoff * lda;
    const __half* Wh = Whi + (size_t)z * wstride;

    const int arow = tid >> 1, acol = (tid & 1) * 16;
    const int brow = tid >> 2, bcol = (tid & 3) * 8;
    const bool bv = (n0 + brow) < N;

    const __half* agh = Ah + (size_t)(m0 + arow) * lda + acol;
    const __half* bgh = Wh + (size_t)(n0 + brow) * ldb + bcol;

    unsigned int sbase = (unsigned int)__cvta_generic_to_shared(sm);
    const int a_dst = arow * ASTR + acol;
    const int b_dst = brow * ASTR + bcol;

    float acc[2][4][4];
    #pragma unroll
    for (int i = 0; i < 2; i++)
        #pragma unroll
        for (int j = 0; j < 4; j++)
            #pragma unroll
            for (int r = 0; r < 4; r++) acc[i][j][r] = 0.0f;

    const int aoff = (wm * 32 + (lane & 15)) * ASTR + (lane >> 4) * 8;
    const int boff = (wn * 32 + ((lane >> 4) << 3) + (lane & 7)) * ASTR
                   + ((lane >> 3) & 1) * 8;

    const int nk = K / 32;

    auto issue = [&](int s) {
        int k0 = s * 32;
        unsigned int st = sbase + (unsigned int)(s % NSTAGE) * (STG * 2);
        cp16(st + (a_dst) * 2,           agh + k0,     true);
        cp16(st + (a_dst + 8) * 2,       agh + k0 + 8, true);
        cp16(st + (APL + b_dst) * 2,     bgh + k0,     bv);
    };

    #pragma unroll
    for (int s = 0; s < NSTAGE - 1; s++) {
        if (s < nk) issue(s);
        asm volatile("cp.async.commit_group;\n");
    }

    for (int it = 0; it < nk; it++) {
        asm volatile("cp.async.wait_group %0;\n" :: "n"(NSTAGE - 2));
        __syncthreads();

        int pf = it + NSTAGE - 1;
        if (pf < nk) issue(pf);
        asm volatile("cp.async.commit_group;\n");

        const __half* st = sm + (it % NSTAGE) * STG;
        #pragma unroll
        for (int k16 = 0; k16 < 2; k16++) {
            unsigned int ahif[8];
            unsigned int bhif[8];
            const __half* pa = st + aoff + k16 * 16;
            ldm_x4(&ahif[0], pa);
            ldm_x4(&ahif[4], pa + 16 * ASTR);
            const __half* pb = st + APL + boff + k16 * 16;
            ldm_x4(&bhif[0], pb);
            ldm_x4(&bhif[4], pb + 16 * ASTR);
            #pragma unroll
            for (int mi = 0; mi < 2; mi++) {
                #pragma unroll
                for (int ni = 0; ni < 4; ni++) {
                    mma16816(acc[mi][ni], &ahif[mi * 4], &bhif[ni * 2]);
                }
            }
        }
    }

    // ---- epilogue ----
    #pragma unroll
    for (int mi = 0; mi < 2; mi++) {
        #pragma unroll
        for (int ni = 0; ni < 4; ni++) {
            int mb = m0 + wm * 32 + mi * 16 + (lane >> 2);
            int nb = n0 + wn * 32 + ni * 8 + (lane & 3) * 2;
            #pragma unroll
            for (int r = 0; r < 4; r++) {
                int mloc = mb + ((r >> 1) << 3);
                int n = nb + (r & 1);
                if (n >= N) continue;
                int m = rowoff + mloc;
                float v = acc[mi][ni][r];
                if (mode == 1)      v += bias[z * bstride + n];
                else if (mode == 2) v = siluf_(v);
                else if (mode == 3) v = sigmoidf_(v) * e1[(size_t)m * lde1 + n]
                                                     * siluf_(e2[(size_t)m * lde2 + n]);
                else if (mode == 4) v += e1[(size_t)m * lde1 + n];
                size_t o = (size_t)m * ldc + n;
                if (Cf)  Cf[o] = v;
                if (Chi) Chi[o] = __float2half(v);
            }
        }
    }
}

// ---------------- downsample by 2 ----------------
__global__ void down2(const float* __restrict__ src, int lds,
                      float* __restrict__ dst, int Tout)
{
    int idx = blockIdx.x * blockDim.x + threadIdx.x;
    int total = NB * Tout * DIN;
    if (idx >= total) return;
    int d = idx & (DIN - 1);
    int t = (idx >> 10) % Tout;
    int b = idx / (Tout * DIN);
    const float* p = src + (size_t)(b * 2 * Tout + 2 * t) * lds + d;
    dst[idx] = 0.5f * (p[0] + p[lds]);
}

// ---------------- depthwise causal conv (K=4) + bias + SiLU, batched ----------------
__global__ void conv_batched(const float* __restrict__ cw,
                             const float* __restrict__ cb)
{
    int z = blockIdx.y;
    int Tl = TLEN >> z;
    int total = NB * Tl * DIN;
    int idx = blockIdx.x * blockDim.x + threadIdx.x;
    if (idx >= total) return;
    const float* xin = (z == 0) ? g_xz : ((z == 1) ? g_xs1 : g_xs2);
    int ldx = (z == 0) ? 2 * DIN : DIN;
    size_t roff = (z == 0) ? 0 : ((z == 1) ? (size_t)R0 * DIN : (size_t)(R0 + R1) * DIN);
    const float* w = cw + z * DIN * 4;
    const float* bias = cb + z * DIN;

    int d = idx & (DIN - 1);
    int t = (idx >> 10) % Tl;
    int b = idx / (Tl * DIN);
    const float* base = xin + (size_t)(b * Tl) * ldx + d;
    float acc = bias[d];
    #pragma unroll
    for (int k = 0; k < 4; k++) {
        int tt = t + k - 3;
        if (tt >= 0) acc = fmaf(w[d * 4 + k], base[(size_t)tt * ldx], acc);
    }
    float v = siluf_(acc);
    g_xc[roff + idx] = v;
    g_xcH[roff + idx] = __float2half(v);
}

// ---------------- selective scan, batched ----------------
__global__ void scan_batched(const float* __restrict__ A_log,
                             const float* __restrict__ Dp)
{
    const int z = blockIdx.y;
    const int Tl = TLEN >> z;
    const size_t roff  = (z == 0) ? 0 : ((z == 1) ? (size_t)R0 : (size_t)(R0 + R1));
    const float* xc   = g_xc   + roff * DIN;
    const float* proj = g_proj + roff * NPROJ;
    const float* dt   = g_dt   + roff * DIN;
    float*       y    = g_y    + roff * DIN;
    const float* Al   = A_log + z * DIN * DSTATE;
    const float* Dz   = Dp + z * DIN;

    const int j    = threadIdx.x & 15;
    const int dloc = threadIdx.x >> 4;
    const int b    = blockIdx.x >> 6;
    const int d0   = (blockIdx.x & 63) * 16;
    const int d    = d0 + dloc;

    __shared__ float s_dt[64][16];
    __shared__ float s_xc[64][16];
    __shared__ float s_B [64][17];
    __shared__ float s_C [64][17];

    const float Aj = -expf(Al[d * 16 + j]);
    const float Dv = Dz[d];
    float h = 0.0f;

    for (int t0 = 0; t0 < Tl; t0 += 64) {
        for (int i = threadIdx.x; i < 64 * 16; i += 256) {
            int tt = i >> 4, dl = i & 15;
            size_t rbase = (size_t)(b * Tl + t0 + tt);
            s_dt[tt][dl] = softplusf_(dt[rbase * DIN + d0 + dl]);
            s_xc[tt][dl] = xc[rbase * DIN + d0 + dl];
            const float* pr = proj + rbase * NPROJ;
            s_B[tt][dl] = pr[DTRANK + dl];
            s_C[tt][dl] = pr[DTRANK + DSTATE + dl];
        }
        __syncthreads();
        #pragma unroll 4
        for (int tt = 0; tt < 64; tt++) {
            float dtv = s_dt[tt][dloc];
            float xcv = s_xc[tt][dloc];
            float dA  = fmaxf(fexp(dtv * Aj), 1e-38f);
            float dBx = fmaxf(dtv * s_B[tt][j] * xcv, 1e-38f);
            h = fmaf(dA, h, dBx);
            float part = s_C[tt][j] * h;
            part += __shfl_xor_sync(0xffffffffu, part, 8);
            part += __shfl_xor_sync(0xffffffffu, part, 4);
            part += __shfl_xor_sync(0xffffffffu, part, 2);
            part += __shfl_xor_sync(0xffffffffu, part, 1);
            if (j == 0)
                y[(size_t)(b * Tl + t0 + tt) * DIN + d] = fmaf(Dv, xcv, part);
        }
        __syncthreads();
    }
}

// ---------------- softmax of scale weights ----------------
__global__ void compute_w(const float* __restrict__ sw)
{
    float a = sw[0], b = sw[1], c = sw[2];
    float m = fmaxf(a, fmaxf(b, c));
    float ea = expf(a - m), eb = expf(b - m), ec = expf(c - m);
    float s = ea + eb + ec;
    g_w[0] = ea / s; g_w[1] = eb / s; g_w[2] = ec / s;
}

// ---------------- fuse ----------------
__global__ void fuse_kernel()
{
    int idx = blockIdx.x * blockDim.x + threadIdx.x;
    int d = idx & (DIN - 1);
    int t = (idx >> 10) & (TLEN - 1);
    int b = idx >> 20;
    float o0 = g_y[idx];
    float o1 = g_y[(size_t)R0 * DIN + (size_t)(b * (TLEN/2) + (t >> 1)) * DIN + d];
    float o2 = g_y[(size_t)(R0 + R1) * DIN + (size_t)(b * (TLEN/4) + (t >> 2)) * DIN + d];
    g_fused[idx] = g_w[0] * o0 + g_w[1] * o1 + g_w[2] * o2;
    float c = (o0 + o1 + o2) * (1.0f / 3.0f);
    g_cth[idx] = __float2half(c);
}

// ---------------- LayerNorm ----------------
__global__ void ln_kernel(const float* __restrict__ gamma,
                          const float* __restrict__ beta,
                          float* __restrict__ out)
{
    int row = blockIdx.x;
    int tid = threadIdx.x;
    const float* r = g_pre + (size_t)row * DMODEL;
    float v1 = r[tid], v2 = r[tid + 256];
    float s  = v1 + v2;
    float q  = v1 * v1 + v2 * v2;
    #pragma unroll
    for (int o = 16; o > 0; o >>= 1) {
        s += __shfl_xor_sync(0xffffffffu, s, o);
        q += __shfl_xor_sync(0xffffffffu, q, o);
    }
    __shared__ float sh[8], sh2[8];
    int wid = tid >> 5, lane = tid & 31;
    if (lane == 0) { sh[wid] = s; sh2[wid] = q; }
    __syncthreads();
    if (tid == 0) {
        float ts = 0.f, tq = 0.f;
        #pragma unroll
        for (int i = 0; i < 8; i++) { ts += sh[i]; tq += sh2[i]; }
        sh[0] = ts; sh2[0] = tq;
    }
    __syncthreads();
    float mu  = sh[0] * (1.0f / DMODEL);
    float var = sh2[0] * (1.0f / DMODEL) - mu * mu;
    float inv = rsqrtf(var + 1e-5f);
    float* o = out + (size_t)row * DMODEL;
    o[tid]       = (v1 - mu) * inv * gamma[tid]       + beta[tid];
    o[tid + 256] = (v2 - mu) * inv * gamma[tid + 256] + beta[tid + 256];
}

// ---------------- driver ----------------
extern "C" void kernel_launch(void* const* d_in, const int* in_sizes, int n_in,
                              void* d_out, int out_size)
{
    const float* x        = (const float*)d_in[0];
    const float* in_proj  = (const float*)d_in[1];
    const float* conv_w   = (const float*)d_in[2];
    const float* conv_b   = (const float*)d_in[3];
    const float* xproj_w  = (const float*)d_in[4];
    const float* dtproj_w = (const float*)d_in[5];
    const float* dtproj_b = (const float*)d_in[6];
    const float* A_log    = (const float*)d_in[7];
    const float* D_p      = (const float*)d_in[8];
    const float* sw       = (const float*)d_in[9];
    const float* cg_w1    = (const float*)d_in[10];
    const float* cg_w2    = (const float*)d_in[11];
    const float* out_w    = (const float*)d_in[12];
    const float* ln_g     = (const float*)d_in[13];
    const float* ln_b     = (const float*)d_in[14];
    float* out            = (float*)d_out;

    static bool attr_set = false;
    if (!attr_set) {
        cudaFuncSetAttribute(gemm_f16, cudaFuncAttributeMaxDynamicSharedMemorySize,
                             SMEM_BYTES);
        attr_set = true;
    }

    float *xz, *xs1, *xs2, *proj, *dtb, *fused, *pre;
    __half *xh,*wih,*xph,*dwh,*c1h,*c2h,*owh;
    __half *xcH,*pH,*cth,*h1h,*ach;
    cudaGetSymbolAddress((void**)&xz,   g_xz);
    cudaGetSymbolAddress((void**)&xs1,  g_xs1);
    cudaGetSymbolAddress((void**)&xs2,  g_xs2);
    cudaGetSymbolAddress((void**)&proj, g_proj);
    cudaGetSymbolAddress((void**)&dtb,  g_dt);
    cudaGetSymbolAddress((void**)&fused,g_fused);
    cudaGetSymbolAddress((void**)&pre,  g_pre);
    cudaGetSymbolAddress((void**)&xh,  g_xh);
    cudaGetSymbolAddress((void**)&wih, g_wih);
    cudaGetSymbolAddress((void**)&xph, g_xph);
    cudaGetSymbolAddress((void**)&dwh, g_dwh);
    cudaGetSymbolAddress((void**)&c1h, g_c1h);
    cudaGetSymbolAddress((void**)&c2h, g_c2h);
    cudaGetSymbolAddress((void**)&owh, g_owh);
    cudaGetSymbolAddress((void**)&xcH, g_xcH);
    cudaGetSymbolAddress((void**)&pH,  g_pH);
    cudaGetSymbolAddress((void**)&cth, g_cth);
    cudaGetSymbolAddress((void**)&h1h, g_h1h);
    cudaGetSymbolAddress((void**)&ach, g_ach);

    const int4 M1   = make_int4(R0, 0, 0, 0);
    const int4 OFF0 = make_int4(0, 0, 0, 0);
    const int4 M3   = make_int4(R0, R1, R2, 0);
    const int4 OFF3 = make_int4(0, R0, R0 + R1, 0);

    // 0. convert inputs + weights to fp16 planes
    split_all<<<(CU6/4 + 255)/256, 256>>>(x, in_proj, xproj_w, dtproj_w,
                                          cg_w1, cg_w2, out_w);

    // 1. in_proj
    gemm_f16<<<dim3(32, 16, 1), 256, SMEM_BYTES>>>(
        xh, DMODEL, wih, DMODEL, 0,
        xz, nullptr, 2*DIN, M1, OFF0, 2*DIN, DMODEL,
        nullptr, 0, 0, nullptr, 0, nullptr, 0);

    // 2. downsample
    down2<<<(R1*DIN)/256, 256>>>(xz, 2*DIN, xs1, TLEN/2);
    down2<<<(R2*DIN)/256, 256>>>(xs1, DIN,  xs2, TLEN/4);

    // 3. conv (batched)
    conv_batched<<<dim3((R0*DIN)/256, 3), 256>>>(conv_w, conv_b);

    // 4. xproj (batched): N=96, K=1024
    gemm_f16<<<dim3(2, 16, 3), 256, SMEM_BYTES>>>(
        xcH, DIN, xph, DIN, NPROJ*DIN,
        proj, pH, NPROJ, M3, OFF3, NPROJ, DIN,
        nullptr, 0, 0, nullptr, 0, nullptr, 0);

    // 5. dtproj (batched): N=1024, K=64 (+bias)
    gemm_f16<<<dim3(16, 16, 3), 256, SMEM_BYTES>>>(
        pH, NPROJ, dwh, DTRANK, DIN*DTRANK,
        dtb, nullptr, DIN, M3, OFF3, DIN, DTRANK,
        dtproj_b, DIN, 1, nullptr, 0, nullptr, 0);

    // 6. selective scan (batched)
    scan_batched<<<dim3(128, 3), 256>>>(A_log, D_p);

    // 7. fuse
    compute_w<<<1, 1>>>(sw);
    fuse_kernel<<<(R0*DIN)/256, 256>>>();

    // 8. context gate
    gemm_f16<<<dim3(8, 16, 1), 256, SMEM_BYTES>>>(
        cth, DIN, c1h, DIN, 0,
        nullptr, h1h, DIN/2, M1, OFF0, DIN/2, DIN,
        nullptr, 0, 2, nullptr, 0, nullptr, 0);
    gemm_f16<<<dim3(16, 16, 1), 256, SMEM_BYTES>>>(
        h1h, DIN/2, c2h, DIN/2, 0,
        nullptr, ach, DIN, M1, OFF0, DIN, DIN/2,
        nullptr, 0, 3, fused, DIN, xz + DIN, 2*DIN);

    // 9. out_proj + residual
    gemm_f16<<<dim3(8, 16, 1), 256, SMEM_BYTES>>>(
        ach, DIN, owh, DIN, 0,
        pre, nullptr, DMODEL, M1, OFF0, DMODEL, DIN,
        nullptr, 0, 4, x, DMODEL, nullptr, 0);

    // 10. LayerNorm
    ln_kernel<<<R0, 256>>>(ln_g, ln_b, out);
}